// round 14
// baseline (speedup 1.0000x reference)
#include <cuda_runtime.h>
#include <math.h>
#include <float.h>

#define NB 1024   // batch
#define LL 4096   // simulated length
#define PP 8192   // acquired length
#define NT 512    // threads per CTA
#define SPT 8     // L elements per thread per row (LL / NT)
#define PAD(i) ((i) + ((i) >> 4))

// smem layout (dynamic), phases alias:
//   pipeline: scsA float[LL+1] at [0,16388); scsB float[LL+1] at [16400,32804)
//             sw  = float2[LL] at [36864, 69632)
//   FFT:      sf  = float2[8704] at [0, 69632)  (clobbers scsA/scsB/sw)
//   always:   red scratch at [69632, 70144)
#define SCSB_OFF   16400
#define SW_OFF     36864
#define RED_OFF    69632
#define SMEM_TOTAL (RED_OFF + 512)

__device__ __forceinline__ float2 cmulf(float2 a, float2 b) {
    return make_float2(a.x * b.x - a.y * b.y, a.x * b.y + a.y * b.x);
}
__device__ __forceinline__ float2 f2a(float2 a, float2 b) { return make_float2(a.x + b.x, a.y + b.y); }
__device__ __forceinline__ float2 f2s(float2 a, float2 b) { return make_float2(a.x - b.x, a.y - b.y); }
__device__ __forceinline__ float2 cmulc(float2 a, float c, float s) {
    return make_float2(a.x * c - a.y * s, a.x * s + a.y * c);
}
__device__ __forceinline__ float2 rotmi(float2 a) { return make_float2(a.y, -a.x); }  // *(−i)

// ===================== 16-point register DFTs =====================
template<bool INV>
__device__ __forceinline__ void dft16_dif(float2* z) {
    const float s = INV ? 1.0f : -1.0f;
    const float C1 = 0.92387953251128674f, S1 = 0.38268343236508978f, R2 = 0.70710678118654752f;
#define BF1(i0,i1) { float ax=z[i0].x-z[i1].x, ay=z[i0].y-z[i1].y; z[i0].x+=z[i1].x; z[i0].y+=z[i1].y; z[i1].x=ax; z[i1].y=ay; }
#define BFI(i0,i1) { float ax=z[i0].x-z[i1].x, ay=z[i0].y-z[i1].y; z[i0].x+=z[i1].x; z[i0].y+=z[i1].y; z[i1].x=-s*ay; z[i1].y=s*ax; }
#define BFT(i0,i1,tc,ts) { float ax=z[i0].x-z[i1].x, ay=z[i0].y-z[i1].y; z[i0].x+=z[i1].x; z[i0].y+=z[i1].y; z[i1].x=ax*(tc)-ay*(ts); z[i1].y=ax*(ts)+ay*(tc); }
    BF1(0, 8); BFT(1, 9, C1, s * S1); BFT(2, 10, R2, s * R2); BFT(3, 11, S1, s * C1);
    BFI(4, 12); BFT(5, 13, -S1, s * C1); BFT(6, 14, -R2, s * R2); BFT(7, 15, -C1, s * S1);
    BF1(0, 4); BFT(1, 5, R2, s * R2); BFI(2, 6); BFT(3, 7, -R2, s * R2);
    BF1(8, 12); BFT(9, 13, R2, s * R2); BFI(10, 14); BFT(11, 15, -R2, s * R2);
    BF1(0, 2); BFI(1, 3); BF1(4, 6); BFI(5, 7);
    BF1(8, 10); BFI(9, 11); BF1(12, 14); BFI(13, 15);
    BF1(0, 1); BF1(2, 3); BF1(4, 5); BF1(6, 7);
    BF1(8, 9); BF1(10, 11); BF1(12, 13); BF1(14, 15);
#undef BF1
#undef BFI
#undef BFT
}

// forward DIF16 specialized for inputs with z[0],z[1],z[9..15] == 0 (only z[2..8] live)
__device__ __forceinline__ void dft16_dif_sparse(float2* z) {
    const float C1 = 0.92387953251128674f, S1 = 0.38268343236508978f, R2 = 0.70710678118654752f;
    float2 y0 = z[8];
    float2 y8 = make_float2(-z[8].x, -z[8].y);
    float2 y2 = z[2], y10 = cmulc(z[2],  R2, -R2);
    float2 y3 = z[3], y11 = cmulc(z[3],  S1, -C1);
    float2 y4 = z[4], y12 = rotmi(z[4]);
    float2 y5 = z[5], y13 = cmulc(z[5], -S1, -C1);
    float2 y6 = z[6], y14 = cmulc(z[6], -R2, -R2);
    float2 y7 = z[7], y15 = cmulc(z[7], -C1, -S1);
    z[0] = f2a(y0, y4);   z[4]  = f2s(y0, y4);
    z[1] = y5;            z[5]  = cmulc(y5, -R2,  R2);
    z[2] = f2a(y2, y6);   z[6]  = rotmi(f2s(y2, y6));
    z[3] = f2a(y3, y7);   z[7]  = cmulc(f2s(y3, y7), -R2, -R2);
    z[8] = f2a(y8, y12);  z[12] = f2s(y8, y12);
    z[9] = y13;           z[13] = cmulc(y13, -R2,  R2);
    z[10] = f2a(y10, y14); z[14] = rotmi(f2s(y10, y14));
    z[11] = f2a(y11, y15); z[15] = cmulc(f2s(y11, y15), -R2, -R2);
#define BF1(i0,i1) { float ax=z[i0].x-z[i1].x, ay=z[i0].y-z[i1].y; z[i0].x+=z[i1].x; z[i0].y+=z[i1].y; z[i1].x=ax; z[i1].y=ay; }
#define BFIF(i0,i1) { float ax=z[i0].x-z[i1].x, ay=z[i0].y-z[i1].y; z[i0].x+=z[i1].x; z[i0].y+=z[i1].y; z[i1].x=ay; z[i1].y=-ax; }
    BF1(0, 2); BFIF(1, 3); BF1(4, 6); BFIF(5, 7);
    BF1(8, 10); BFIF(9, 11); BF1(12, 14); BFIF(13, 15);
    BF1(0, 1); BF1(2, 3); BF1(4, 5); BF1(6, 7);
    BF1(8, 9); BF1(10, 11); BF1(12, 13); BF1(14, 15);
#undef BF1
#undef BFIF
}

template<bool INV>
__device__ __forceinline__ void dft16_dit(float2* z) {
    const float s = INV ? 1.0f : -1.0f;
    const float C1 = 0.92387953251128674f, S1 = 0.38268343236508978f, R2 = 0.70710678118654752f;
#define BT1(i0,i1) { float bx=z[i1].x, by=z[i1].y; z[i1].x=z[i0].x-bx; z[i1].y=z[i0].y-by; z[i0].x+=bx; z[i0].y+=by; }
#define BTI(i0,i1) { float bx=-s*z[i1].y, by=s*z[i1].x; z[i1].x=z[i0].x-bx; z[i1].y=z[i0].y-by; z[i0].x+=bx; z[i0].y+=by; }
#define BTT(i0,i1,tc,ts) { float bx=z[i1].x*(tc)-z[i1].y*(ts), by=z[i1].x*(ts)+z[i1].y*(tc); z[i1].x=z[i0].x-bx; z[i1].y=z[i0].y-by; z[i0].x+=bx; z[i0].y+=by; }
    BT1(0, 1); BT1(2, 3); BT1(4, 5); BT1(6, 7);
    BT1(8, 9); BT1(10, 11); BT1(12, 13); BT1(14, 15);
    BT1(0, 2); BTI(1, 3); BT1(4, 6); BTI(5, 7);
    BT1(8, 10); BTI(9, 11); BT1(12, 14); BTI(13, 15);
    BT1(0, 4); BTT(1, 5, R2, s * R2); BTI(2, 6); BTT(3, 7, -R2, s * R2);
    BT1(8, 12); BTT(9, 13, R2, s * R2); BTI(10, 14); BTT(11, 15, -R2, s * R2);
    BT1(0, 8); BTT(1, 9, C1, s * S1); BTT(2, 10, R2, s * R2); BTT(3, 11, S1, s * C1);
    BTI(4, 12); BTT(5, 13, -S1, s * C1); BTT(6, 14, -R2, s * R2); BTT(7, 15, -C1, s * S1);
#undef BT1
#undef BTI
#undef BTT
}

// ===================== block helpers (512 threads = 16 warps) =====================
__device__ __forceinline__ float2 scan2_bc(float2 v, float2 v0, float2* ws, int tid,
                                           float2* r0_out, float2* tot_out) {
    __syncthreads();
    int lane = tid & 31, wp = tid >> 5;
    if (tid == 0) ws[17] = v0;
    float2 x = v;
#pragma unroll
    for (int d = 1; d < 32; d <<= 1) {
        float yx = __shfl_up_sync(0xffffffffu, x.x, d);
        float yy = __shfl_up_sync(0xffffffffu, x.y, d);
        if (lane >= d) { x.x += yx; x.y += yy; }
    }
    if (lane == 31) ws[wp] = x;
    __syncthreads();
    if (wp == 0) {
        float2 t = (lane < 16) ? ws[lane] : make_float2(0.f, 0.f);
#pragma unroll
        for (int d = 1; d < 16; d <<= 1) {
            float yx = __shfl_up_sync(0xffffffffu, t.x, d);
            float yy = __shfl_up_sync(0xffffffffu, t.y, d);
            if (lane >= d) { t.x += yx; t.y += yy; }
        }
        if (lane < 16) ws[lane] = t;
    }
    __syncthreads();
    float2 off = (wp > 0) ? ws[wp - 1] : make_float2(0.f, 0.f);
    *r0_out = ws[17];
    *tot_out = ws[15];
    return f2a(x, off);
}

__device__ __forceinline__ float2 scan2(float2 v, float2* ws, int tid) {
    __syncthreads();
    int lane = tid & 31, wp = tid >> 5;
    float2 x = v;
#pragma unroll
    for (int d = 1; d < 32; d <<= 1) {
        float yx = __shfl_up_sync(0xffffffffu, x.x, d);
        float yy = __shfl_up_sync(0xffffffffu, x.y, d);
        if (lane >= d) { x.x += yx; x.y += yy; }
    }
    if (lane == 31) ws[wp] = x;
    __syncthreads();
    if (wp == 0) {
        float2 t = (lane < 16) ? ws[lane] : make_float2(0.f, 0.f);
#pragma unroll
        for (int d = 1; d < 16; d <<= 1) {
            float yx = __shfl_up_sync(0xffffffffu, t.x, d);
            float yy = __shfl_up_sync(0xffffffffu, t.y, d);
            if (lane >= d) { t.x += yx; t.y += yy; }
        }
        if (lane < 16) ws[lane] = t;
    }
    __syncthreads();
    float2 off = (wp > 0) ? ws[wp - 1] : make_float2(0.f, 0.f);
    return f2a(x, off);
}

__device__ __forceinline__ float4 rmax4(float4 v, float4* ws, int tid) {
    __syncthreads();
    int lane = tid & 31, wp = tid >> 5;
#pragma unroll
    for (int d = 16; d > 0; d >>= 1) {
        v.x = fmaxf(v.x, __shfl_xor_sync(0xffffffffu, v.x, d));
        v.y = fmaxf(v.y, __shfl_xor_sync(0xffffffffu, v.y, d));
        v.z = fmaxf(v.z, __shfl_xor_sync(0xffffffffu, v.z, d));
        v.w = fmaxf(v.w, __shfl_xor_sync(0xffffffffu, v.w, d));
    }
    if (lane == 0) ws[wp] = v;
    __syncthreads();
    if (wp == 0) {
        float4 t = (lane < 16) ? ws[lane]
                               : make_float4(-FLT_MAX, -FLT_MAX, -FLT_MAX, -FLT_MAX);
#pragma unroll
        for (int d = 8; d > 0; d >>= 1) {
            t.x = fmaxf(t.x, __shfl_xor_sync(0xffffffffu, t.x, d));
            t.y = fmaxf(t.y, __shfl_xor_sync(0xffffffffu, t.y, d));
            t.z = fmaxf(t.z, __shfl_xor_sync(0xffffffffu, t.z, d));
            t.w = fmaxf(t.w, __shfl_xor_sync(0xffffffffu, t.w, d));
        }
        if (lane == 0) ws[16] = t;
    }
    __syncthreads();
    return ws[16];
}

__device__ __forceinline__ float2 rmax2(float2 v, float2* ws, int tid) {
    __syncthreads();
    int lane = tid & 31, wp = tid >> 5;
#pragma unroll
    for (int d = 16; d > 0; d >>= 1) {
        v.x = fmaxf(v.x, __shfl_xor_sync(0xffffffffu, v.x, d));
        v.y = fmaxf(v.y, __shfl_xor_sync(0xffffffffu, v.y, d));
    }
    if (lane == 0) ws[wp] = v;
    __syncthreads();
    if (wp == 0) {
        float2 t = (lane < 16) ? ws[lane] : make_float2(-FLT_MAX, -FLT_MAX);
#pragma unroll
        for (int d = 8; d > 0; d >>= 1) {
            t.x = fmaxf(t.x, __shfl_xor_sync(0xffffffffu, t.x, d));
            t.y = fmaxf(t.y, __shfl_xor_sync(0xffffffffu, t.y, d));
        }
        if (lane == 0) ws[16] = t;
    }
    __syncthreads();
    return ws[16];
}

// pair-chained twiddle-and-store for forward DIF passes
#define TW_STORE_FWD(IDX_EXPR)                                            \
    {                                                                     \
        sf[IDX_EXPR(0)] = z[0];                                           \
        sf[IDX_EXPR(1)] = cmulf(z[8], tb);                                \
        const float2 t2 = cmulf(tb, tb);                                  \
        float2 cur = t2;                                                  \
        sf[IDX_EXPR(2)] = cmulf(z[rv[2]], cur);                           \
        sf[IDX_EXPR(3)] = cmulf(z[rv[3]], cmulf(cur, tb));                \
        _Pragma("unroll")                                                 \
        for (int q = 4; q < 16; q += 2) {                                 \
            cur = cmulf(cur, t2);                                         \
            sf[IDX_EXPR(q)] = cmulf(z[rv[q]], cur);                       \
            sf[IDX_EXPR(q + 1)] = cmulf(z[rv[q + 1]], cmulf(cur, tb));    \
        }                                                                 \
    }

// pair-chained input twiddles for inverse DIT passes: z[m] *= tbc^m
#define TW_APPLY_INV()                                                    \
    {                                                                     \
        z[1] = cmulf(z[1], tbc);                                          \
        const float2 t2 = cmulf(tbc, tbc);                                \
        float2 cur = t2;                                                  \
        z[2] = cmulf(z[2], cur);                                          \
        z[3] = cmulf(z[3], cmulf(cur, tbc));                              \
        _Pragma("unroll")                                                 \
        for (int m = 4; m < 16; m += 2) {                                 \
            cur = cmulf(cur, t2);                                         \
            z[m] = cmulf(z[m], cur);                                      \
            z[m + 1] = cmulf(z[m + 1], cmulf(cur, tbc));                  \
        }                                                                 \
    }

// ===================== fused kernel: one CTA per row pair =====================
// occ 3 experiment: 42-reg target, 48 warps/SM (smem 70.1KB*3 = 210KB fits)
__global__ void __launch_bounds__(NT, 3)
pipeline_kernel(const float* __restrict__ g_start, const float* __restrict__ g_end,
                const float* __restrict__ g_std,   const float* __restrict__ g_lb,
                const float* __restrict__ g_ub,    const int*   __restrict__ g_win,
                const float* __restrict__ g_scale, const float* __restrict__ g_noise,
                const float* __restrict__ g_omit,  const float* __restrict__ g_ppm,
                const float* __restrict__ g_range, float* __restrict__ out)
{
    extern __shared__ __align__(16) char smem_raw[];
    float*  scsA = (float*)smem_raw;                       // cumsum row A
    float*  scsB = (float*)(smem_raw + SCSB_OFF);          // cumsum row B
    float2* sw   = (float2*)(smem_raw + SW_OFF);           // smoothed signal
    float2* sf   = (float2*)smem_raw;                      // FFT buffer (aliases)
    float4* red  = (float4*)(smem_raw + RED_OFF);          // reduce scratch
    float2* redb = (float2*)(smem_raw + RED_OFF + 18 * 16);

    const int tid = threadIdx.x;
    const int g   = blockIdx.x;
    const int rA  = 2 * g, rB = 2 * g + 1;
    const int base = tid * SPT;
    const float inv_lm1 = 1.0f / (float)(LL - 1);
    const size_t raw_off = (size_t)NB * 2 * PP;
    const size_t ochA = ((size_t)rA * 2) * PP;
    const size_t ochB = ((size_t)rB * 2) * PP;
    const int rv[16] = {0, 8, 4, 12, 2, 10, 6, 14, 1, 9, 5, 13, 3, 11, 7, 15};

    // ---- out-of-band ch0 zero-fill up front: overlaps the entire pipeline ----
    {
        const float4 zz = make_float4(0.f, 0.f, 0.f, 0.f);
#pragma unroll
        for (int it = 0; it < 3; ++it) {
            int j = tid + it * NT;
            if (j < 1152) {
                int p4 = (j < 256) ? (j << 2) : (4608 + ((j - 256) << 2));
                __stcs((float4*)(out + raw_off + ochA + p4), zz);
                __stcs((float4*)(out + raw_off + ochB + p4), zz);
                __stcs((float4*)(out + ochA + (PP - 4 - p4)), zz);
                __stcs((float4*)(out + ochB + (PP - 4 - p4)), zz);
            }
        }
    }

    // ============== pipeline: both rows at once ==============
    const float sdA = g_std[rA], sdB = g_std[rB];
    float2 vv[SPT];
    {
        const float4* nzA = (const float4*)(g_noise + (size_t)rA * LL + base);
        const float4* nzB = (const float4*)(g_noise + (size_t)rB * LL + base);
        float4 a0 = __ldcs(nzA);
        float4 a1 = __ldcs(nzA + 1);
        float4 b0 = __ldcs(nzB);
        float4 b1 = __ldcs(nzB + 1);
        float ta[SPT] = {a0.x, a0.y, a0.z, a0.w, a1.x, a1.y, a1.z, a1.w};
        float tb[SPT] = {b0.x, b0.y, b0.z, b0.w, b1.x, b1.y, b1.z, b1.w};
        float aA = 0.f, aB = 0.f;
#pragma unroll
        for (int j = 0; j < SPT; ++j) {
            aA += sdA * (ta[j] - 0.5f);
            aB += sdB * (tb[j] - 0.5f);
            vv[j] = make_float2(aA, aB);
        }
    }
    float2 excl, r0, rl;
    {
        float2 incl = scan2_bc(vv[SPT - 1], vv[0], (float2*)red, tid, &r0, &rl);
        excl = f2s(incl, vv[SPT - 1]);
    }

    // detrended deltas: compute ONCE, keep in vv
    float4 mx = make_float4(-FLT_MAX, -FLT_MAX, -FLT_MAX, -FLT_MAX);
#pragma unroll
    for (int j = 0; j < SPT; ++j) {
        float ft = (float)(base + j) * inv_lm1;
        float dA = (vv[j].x + excl.x) - (r0.x + (rl.x - r0.x) * ft);
        float dB = (vv[j].y + excl.y) - (r0.y + (rl.y - r0.y) * ft);
        vv[j] = make_float2(dA, dB);
        mx.x = fmaxf(mx.x, dA); mx.y = fmaxf(mx.y, -dA);
        mx.z = fmaxf(mx.z, dB); mx.w = fmaxf(mx.w, -dB);
    }
    float4 mm = rmax4(mx, red, tid);

    const float loA = g_lb[rA], hiA = g_ub[rA];
    const float loB = g_lb[rB], hiB = g_ub[rB];
    const float invdvA = 1.0f / fmaxf(1.0f, (mm.x + mm.y) / (hiA - loA));
    const float invdvB = 1.0f / fmaxf(1.0f, (mm.z + mm.w) / (hiB - loB));
    const float stA = g_start[rA], enA = g_end[rA];
    const float stB = g_start[rB], enB = g_end[rB];

    // squeeze + reflect + trend from the stored deltas; serial per-thread cumsum
    {
        float aA = 0.f, aB = 0.f;
#pragma unroll
        for (int j = 0; j < SPT; ++j) {
            float ft = (float)(base + j) * inv_lm1;
            {
                float d = vv[j].x * invdvA;
                float tr = stA + (enA - stA) * ft;
                float ub2 = hiA - tr, lb2 = loA - tr;
                float over = d - ub2;
                if (over >= 0.f) d = ub2 - over;
                float under = lb2 - d;
                if (under >= 0.f) d = lb2 + under;
                aA += tr + d;
            }
            {
                float d = vv[j].y * invdvB;
                float tr = stB + (enB - stB) * ft;
                float ub2 = hiB - tr, lb2 = loB - tr;
                float over = d - ub2;
                if (over >= 0.f) d = ub2 - over;
                float under = lb2 - d;
                if (under >= 0.f) d = lb2 + under;
                aB += tr + d;
            }
            vv[j] = make_float2(aA, aB);
        }
    }
    {
        float2 incl = scan2(vv[SPT - 1], (float2*)red, tid);
        float2 ex2 = f2s(incl, vv[SPT - 1]);
#pragma unroll
        for (int j = 0; j < SPT; ++j) {
            scsA[1 + base + j] = vv[j].x + ex2.x;
            scsB[1 + base + j] = vv[j].y + ex2.y;
        }
    }
    if (tid == 0) { scsA[0] = 0.f; scsB[0] = 0.f; }
    __syncthreads();

    const int wA = g_win[rA], wB = g_win[rB];
    const float invwA = 1.0f / (float)wA, invwB = 1.0f / (float)wB;
    const int whA = wA >> 1, whB = wB >> 1;
#pragma unroll
    for (int j = 0; j < SPT; ++j) {
        int t = base + j;
        int loa = max(t - whA, 0), hia = min(t - whA + wA, LL);
        int lob = max(t - whB, 0), hib = min(t - whB + wB, LL);
        float bA = (scsA[hia] - scsA[loa]) * invwA;
        float bB = (scsB[hib] - scsB[lob]) * invwB;
        vv[j] = make_float2(bA, bB);
    }
    if (tid == 0)      redb[0] = vv[0];
    if (tid == NT - 1) redb[1] = vv[SPT - 1];
    __syncthreads();
    const float2 b0v = redb[0], blv = redb[1];

    float2 ab = make_float2(0.f, 0.f);
#pragma unroll
    for (int j = 0; j < SPT; ++j) {
        float ft = (float)(base + j) * inv_lm1;
        float cA = vv[j].x - (b0v.x + (blv.x - b0v.x) * ft);
        float cB = vv[j].y - (b0v.y + (blv.y - b0v.y) * ft);
        vv[j] = make_float2(cA, cB);
        ab.x = fmaxf(ab.x, fabsf(cA));
        ab.y = fmaxf(ab.y, fabsf(cB));
    }
    float2 mr = rmax2(ab, (float2*)red, tid);
    const float facA = g_omit[rA] * g_scale[rA] / ((mr.x == 0.f) ? 1.0f : mr.x);
    const float facB = g_omit[rB] * g_scale[rB] / ((mr.y == 0.f) ? 1.0f : mr.y);
#pragma unroll
    for (int j = 0; j < SPT; ++j)
        sw[base + j] = make_float2(vv[j].x * facA, vv[j].y * facB);
    __syncthreads();

    // ============== fused interp + forward FFT pass A (sparse m=2..8) ==============
    float2 z[16];
#pragma unroll
    for (int m = 0; m < 16; ++m) z[m] = make_float2(0.f, 0.f);
    {
        const float rlo = g_range[0], rhi = g_range[1];
        const float istep = (float)(LL - 1) / (rhi - rlo);
        const float pstep = 12.0f / 8191.0f;   // ppm = linspace(-2, 10, 8192)
#pragma unroll
        for (int m = 2; m <= 8; ++m) {
            int p = tid + (m << 9);
            float xp = fmaf((float)p, pstep, -2.0f);
            float2 v = make_float2(0.f, 0.f);
            if (xp >= rlo && xp <= rhi) {
                float u = (xp - rlo) * istep;
                int i = (int)u;
                if (i > LL - 2) i = LL - 2;
                float f = u - (float)i;
                float2 s0 = sw[i], s1 = sw[i + 1];
                v.x = fmaf(s1.x - s0.x, f, s0.x);
                v.y = fmaf(s1.y - s0.y, f, s0.y);
            }
            z[m] = v;
            __stcs(out + ochA + (PP - 1 - p), v.x);
            __stcs(out + raw_off + ochA + p, v.x);
            __stcs(out + ochB + (PP - 1 - p), v.y);
            __stcs(out + raw_off + ochB + p, v.y);
        }
    }
    dft16_dif_sparse(z);
    {
        const int off = tid;
        float sn, cs;
        __sincosf(-7.66990393942820615e-4f * (float)off, &sn, &cs);  // -2pi/8192
        const float2 tb = make_float2(cs, sn);
        __syncthreads();   // all interp reads of sw complete before sf clobbers it
#define IDXA(q) PAD(((q) << 9) + off)
        TW_STORE_FWD(IDXA)
#undef IDXA
    }
    __syncthreads();   // cross-warp: pass A scatters into every warp's region

    // ---- forward pass B: radix-16, h=32 (warp-local region) ----
    {
        const int off = tid & 31;
        const int b0 = (tid >> 5) << 9;
        float2 zB[16];
#pragma unroll
        for (int m = 0; m < 16; ++m) zB[m] = sf[PAD(b0 + off + (m << 5))];
        float2* z = zB;
        dft16_dif<false>(z);
        float sn, cs;
        __sincosf(-1.22718463030851272e-2f * (float)off, &sn, &cs);  // -2pi/512
        const float2 tb = make_float2(cs, sn);
#define IDXB(q) PAD(b0 + ((q) << 5) + off)
        TW_STORE_FWD(IDXB)
#undef IDXB
    }
    __syncwarp();   // B -> middle is within the warp's own 512-region

    // ---- fused middle: fwd C (r16 h=2) + collapsed r2/Hilbert/r2 + inv C' ----
    {
        const int off = tid & 1;
        const int b0 = (tid >> 1) << 5;
        const float W32C = 0.98078528040323044913f, W32S = -0.19509032201612826785f;
        float2 z[16];
#pragma unroll
        for (int m = 0; m < 16; ++m) z[m] = sf[PAD(b0 + off + (m << 1))];
        dft16_dif<false>(z);
#pragma unroll
        for (int k = 0; k < 16; ++k) {
            z[k].x = __shfl_xor_sync(0xffffffffu, z[k].x, 1);
            z[k].y = __shfl_xor_sync(0xffffffffu, z[k].y, 1);
        }
        if (b0 == 0) z[0] = make_float2(0.f, 0.f);   // spectral positions p = 0, 1
#pragma unroll
        for (int k = 0; k < 16; ++k) z[k] = rotmi(z[k]);
        const float2 tb = make_float2(W32C, off ? -W32S : W32S);
        z[8] = cmulf(z[8], tb);
        {
            const float2 t2 = cmulf(tb, tb);
            float2 cur = t2;
            z[rv[2]] = cmulf(z[rv[2]], cur);
            z[rv[3]] = cmulf(z[rv[3]], cmulf(cur, tb));
#pragma unroll
            for (int q = 4; q < 16; q += 2) {
                cur = cmulf(cur, t2);
                z[rv[q]] = cmulf(z[rv[q]], cur);
                z[rv[q + 1]] = cmulf(z[rv[q + 1]], cmulf(cur, tb));
            }
        }
        dft16_dit<true>(z);
#pragma unroll
        for (int q = 0; q < 16; ++q) sf[PAD(b0 + off + (q << 1))] = z[q];
    }
    __syncwarp();   // middle -> B' is within the warp's own 512-region

    // ---- inverse pass B': radix-16 DIT, h=32 (warp-local) ----
    {
        const int off = tid & 31;
        const int b0 = (tid >> 5) << 9;
        float2 z[16];
#pragma unroll
        for (int m = 0; m < 16; ++m) z[m] = sf[PAD(b0 + off + (m << 5))];
        float sn, cs;
        __sincosf(-1.22718463030851272e-2f * (float)off, &sn, &cs);
        const float2 tbc = make_float2(cs, -sn);
        TW_APPLY_INV()
        dft16_dif<true>(z);
        sf[PAD(b0 + off)] = z[0];
#pragma unroll
        for (int q = 1; q < 16; ++q) sf[PAD(b0 + off + (q << 5))] = z[rv[q]];
    }
    __syncthreads();   // cross-warp: A' gathers stride-512

    // ---- inverse pass A': radix-16 DIT, h=512; write gmem directly ----
    {
        const int off = tid;
        float2 z[16];
#pragma unroll
        for (int m = 0; m < 16; ++m) z[m] = sf[PAD(off + (m << 9))];
        float sn, cs;
        __sincosf(-7.66990393942820615e-4f * (float)off, &sn, &cs);
        const float2 tbc = make_float2(cs, -sn);
        TW_APPLY_INV()
        dft16_dif<true>(z);
        const float invP = 1.0f / 4096.0f;   // 2/8192: middle sandwich factor folded in
        const size_t ch1a = ((size_t)rA * 2 + 1) * PP;
        const size_t ch1b = ((size_t)rB * 2 + 1) * PP;
#pragma unroll
        for (int q = 0; q < 16; ++q) {
            int p = off + (q << 9);
            float hA = z[rv[q]].x * invP;
            float hB = z[rv[q]].y * invP;
            __stcs(out + ch1a + (PP - 1 - p), hA);
            __stcs(out + raw_off + ch1a + p, hA);
            __stcs(out + ch1b + (PP - 1 - p), hB);
            __stcs(out + raw_off + ch1b + p, hB);
        }
    }
}

extern "C" void kernel_launch(void* const* d_in, const int* in_sizes, int n_in,
                              void* d_out, int out_size) {
    const float* g_start = (const float*)d_in[0];
    const float* g_end   = (const float*)d_in[1];
    const float* g_std   = (const float*)d_in[2];
    const float* g_lb    = (const float*)d_in[3];
    const float* g_ub    = (const float*)d_in[4];
    const int*   g_win   = (const int*)  d_in[5];
    const float* g_scale = (const float*)d_in[6];
    const float* g_noise = (const float*)d_in[7];
    const float* g_omit  = (const float*)d_in[8];
    const float* g_ppm   = (const float*)d_in[9];
    const float* g_range = (const float*)d_in[10];
    float* out = (float*)d_out;

    cudaFuncSetAttribute(pipeline_kernel,
                         cudaFuncAttributeMaxDynamicSharedMemorySize, SMEM_TOTAL);
    pipeline_kernel<<<NB / 2, NT, SMEM_TOTAL>>>(
        g_start, g_end, g_std, g_lb, g_ub, g_win, g_scale, g_noise,
        g_omit, g_ppm, g_range, out);
}

// round 15
// speedup vs baseline: 1.2909x; 1.2909x over previous
#include <cuda_runtime.h>
#include <math.h>
#include <float.h>

#define NB 1024   // batch
#define LL 4096   // simulated length
#define PP 8192   // acquired length
#define NT 512    // threads per CTA
#define SPT 8     // L elements per thread per row (LL / NT)
#define PAD(i) ((i) + ((i) >> 4))

// smem layout (dynamic), phases alias:
//   pipeline: scsA float[LL+1] at [0,16388); scsB float[LL+1] at [16400,32804)
//             sw  = float2[LL] at [36864, 69632)
//   FFT:      sf  = float2[8704] at [0, 69632)  (clobbers scsA/scsB/sw)
//   always:   red scratch at [69632, 70144)
#define SCSB_OFF   16400
#define SW_OFF     36864
#define RED_OFF    69632
#define SMEM_TOTAL (RED_OFF + 512)

__device__ __forceinline__ float2 cmulf(float2 a, float2 b) {
    return make_float2(a.x * b.x - a.y * b.y, a.x * b.y + a.y * b.x);
}
__device__ __forceinline__ float2 f2a(float2 a, float2 b) { return make_float2(a.x + b.x, a.y + b.y); }
__device__ __forceinline__ float2 f2s(float2 a, float2 b) { return make_float2(a.x - b.x, a.y - b.y); }
__device__ __forceinline__ float2 cmulc(float2 a, float c, float s) {
    return make_float2(a.x * c - a.y * s, a.x * s + a.y * c);
}
__device__ __forceinline__ float2 rotmi(float2 a) { return make_float2(a.y, -a.x); }  // *(−i)

// ===================== 16-point register DFTs =====================
template<bool INV>
__device__ __forceinline__ void dft16_dif(float2* z) {
    const float s = INV ? 1.0f : -1.0f;
    const float C1 = 0.92387953251128674f, S1 = 0.38268343236508978f, R2 = 0.70710678118654752f;
#define BF1(i0,i1) { float ax=z[i0].x-z[i1].x, ay=z[i0].y-z[i1].y; z[i0].x+=z[i1].x; z[i0].y+=z[i1].y; z[i1].x=ax; z[i1].y=ay; }
#define BFI(i0,i1) { float ax=z[i0].x-z[i1].x, ay=z[i0].y-z[i1].y; z[i0].x+=z[i1].x; z[i0].y+=z[i1].y; z[i1].x=-s*ay; z[i1].y=s*ax; }
#define BFT(i0,i1,tc,ts) { float ax=z[i0].x-z[i1].x, ay=z[i0].y-z[i1].y; z[i0].x+=z[i1].x; z[i0].y+=z[i1].y; z[i1].x=ax*(tc)-ay*(ts); z[i1].y=ax*(ts)+ay*(tc); }
    BF1(0, 8); BFT(1, 9, C1, s * S1); BFT(2, 10, R2, s * R2); BFT(3, 11, S1, s * C1);
    BFI(4, 12); BFT(5, 13, -S1, s * C1); BFT(6, 14, -R2, s * R2); BFT(7, 15, -C1, s * S1);
    BF1(0, 4); BFT(1, 5, R2, s * R2); BFI(2, 6); BFT(3, 7, -R2, s * R2);
    BF1(8, 12); BFT(9, 13, R2, s * R2); BFI(10, 14); BFT(11, 15, -R2, s * R2);
    BF1(0, 2); BFI(1, 3); BF1(4, 6); BFI(5, 7);
    BF1(8, 10); BFI(9, 11); BF1(12, 14); BFI(13, 15);
    BF1(0, 1); BF1(2, 3); BF1(4, 5); BF1(6, 7);
    BF1(8, 9); BF1(10, 11); BF1(12, 13); BF1(14, 15);
#undef BF1
#undef BFI
#undef BFT
}

// forward DIF16 specialized for inputs with z[0],z[1],z[9..15] == 0 (only z[2..8] live)
__device__ __forceinline__ void dft16_dif_sparse(float2* z) {
    const float C1 = 0.92387953251128674f, S1 = 0.38268343236508978f, R2 = 0.70710678118654752f;
    float2 y0 = z[8];
    float2 y8 = make_float2(-z[8].x, -z[8].y);
    float2 y2 = z[2], y10 = cmulc(z[2],  R2, -R2);
    float2 y3 = z[3], y11 = cmulc(z[3],  S1, -C1);
    float2 y4 = z[4], y12 = rotmi(z[4]);
    float2 y5 = z[5], y13 = cmulc(z[5], -S1, -C1);
    float2 y6 = z[6], y14 = cmulc(z[6], -R2, -R2);
    float2 y7 = z[7], y15 = cmulc(z[7], -C1, -S1);
    z[0] = f2a(y0, y4);   z[4]  = f2s(y0, y4);
    z[1] = y5;            z[5]  = cmulc(y5, -R2,  R2);
    z[2] = f2a(y2, y6);   z[6]  = rotmi(f2s(y2, y6));
    z[3] = f2a(y3, y7);   z[7]  = cmulc(f2s(y3, y7), -R2, -R2);
    z[8] = f2a(y8, y12);  z[12] = f2s(y8, y12);
    z[9] = y13;           z[13] = cmulc(y13, -R2,  R2);
    z[10] = f2a(y10, y14); z[14] = rotmi(f2s(y10, y14));
    z[11] = f2a(y11, y15); z[15] = cmulc(f2s(y11, y15), -R2, -R2);
#define BF1(i0,i1) { float ax=z[i0].x-z[i1].x, ay=z[i0].y-z[i1].y; z[i0].x+=z[i1].x; z[i0].y+=z[i1].y; z[i1].x=ax; z[i1].y=ay; }
#define BFIF(i0,i1) { float ax=z[i0].x-z[i1].x, ay=z[i0].y-z[i1].y; z[i0].x+=z[i1].x; z[i0].y+=z[i1].y; z[i1].x=ay; z[i1].y=-ax; }
    BF1(0, 2); BFIF(1, 3); BF1(4, 6); BFIF(5, 7);
    BF1(8, 10); BFIF(9, 11); BF1(12, 14); BFIF(13, 15);
    BF1(0, 1); BF1(2, 3); BF1(4, 5); BF1(6, 7);
    BF1(8, 9); BF1(10, 11); BF1(12, 13); BF1(14, 15);
#undef BF1
#undef BFIF
}

template<bool INV>
__device__ __forceinline__ void dft16_dit(float2* z) {
    const float s = INV ? 1.0f : -1.0f;
    const float C1 = 0.92387953251128674f, S1 = 0.38268343236508978f, R2 = 0.70710678118654752f;
#define BT1(i0,i1) { float bx=z[i1].x, by=z[i1].y; z[i1].x=z[i0].x-bx; z[i1].y=z[i0].y-by; z[i0].x+=bx; z[i0].y+=by; }
#define BTI(i0,i1) { float bx=-s*z[i1].y, by=s*z[i1].x; z[i1].x=z[i0].x-bx; z[i1].y=z[i0].y-by; z[i0].x+=bx; z[i0].y+=by; }
#define BTT(i0,i1,tc,ts) { float bx=z[i1].x*(tc)-z[i1].y*(ts), by=z[i1].x*(ts)+z[i1].y*(tc); z[i1].x=z[i0].x-bx; z[i1].y=z[i0].y-by; z[i0].x+=bx; z[i0].y+=by; }
    BT1(0, 1); BT1(2, 3); BT1(4, 5); BT1(6, 7);
    BT1(8, 9); BT1(10, 11); BT1(12, 13); BT1(14, 15);
    BT1(0, 2); BTI(1, 3); BT1(4, 6); BTI(5, 7);
    BT1(8, 10); BTI(9, 11); BT1(12, 14); BTI(13, 15);
    BT1(0, 4); BTT(1, 5, R2, s * R2); BTI(2, 6); BTT(3, 7, -R2, s * R2);
    BT1(8, 12); BTT(9, 13, R2, s * R2); BTI(10, 14); BTT(11, 15, -R2, s * R2);
    BT1(0, 8); BTT(1, 9, C1, s * S1); BTT(2, 10, R2, s * R2); BTT(3, 11, S1, s * C1);
    BTI(4, 12); BTT(5, 13, -S1, s * C1); BTT(6, 14, -R2, s * R2); BTT(7, 15, -C1, s * S1);
#undef BT1
#undef BTI
#undef BTT
}

// ===================== block helpers (512 threads = 16 warps) =====================
// FIRST=true skips the leading barrier (safe only when ws has no prior writer)
template<bool FIRST>
__device__ __forceinline__ float2 scan2_bc(float2 v, float2 v0, float2* ws, int tid,
                                           float2* r0_out, float2* tot_out) {
    if (!FIRST) __syncthreads();
    int lane = tid & 31, wp = tid >> 5;
    if (tid == 0) ws[17] = v0;
    float2 x = v;
#pragma unroll
    for (int d = 1; d < 32; d <<= 1) {
        float yx = __shfl_up_sync(0xffffffffu, x.x, d);
        float yy = __shfl_up_sync(0xffffffffu, x.y, d);
        if (lane >= d) { x.x += yx; x.y += yy; }
    }
    if (lane == 31) ws[wp] = x;
    __syncthreads();
    if (wp == 0) {
        float2 t = (lane < 16) ? ws[lane] : make_float2(0.f, 0.f);
#pragma unroll
        for (int d = 1; d < 16; d <<= 1) {
            float yx = __shfl_up_sync(0xffffffffu, t.x, d);
            float yy = __shfl_up_sync(0xffffffffu, t.y, d);
            if (lane >= d) { t.x += yx; t.y += yy; }
        }
        if (lane < 16) ws[lane] = t;
    }
    __syncthreads();
    float2 off = (wp > 0) ? ws[wp - 1] : make_float2(0.f, 0.f);
    *r0_out = ws[17];
    *tot_out = ws[15];
    return f2a(x, off);
}

__device__ __forceinline__ float2 scan2(float2 v, float2* ws, int tid) {
    __syncthreads();
    int lane = tid & 31, wp = tid >> 5;
    float2 x = v;
#pragma unroll
    for (int d = 1; d < 32; d <<= 1) {
        float yx = __shfl_up_sync(0xffffffffu, x.x, d);
        float yy = __shfl_up_sync(0xffffffffu, x.y, d);
        if (lane >= d) { x.x += yx; x.y += yy; }
    }
    if (lane == 31) ws[wp] = x;
    __syncthreads();
    if (wp == 0) {
        float2 t = (lane < 16) ? ws[lane] : make_float2(0.f, 0.f);
#pragma unroll
        for (int d = 1; d < 16; d <<= 1) {
            float yx = __shfl_up_sync(0xffffffffu, t.x, d);
            float yy = __shfl_up_sync(0xffffffffu, t.y, d);
            if (lane >= d) { t.x += yx; t.y += yy; }
        }
        if (lane < 16) ws[lane] = t;
    }
    __syncthreads();
    float2 off = (wp > 0) ? ws[wp - 1] : make_float2(0.f, 0.f);
    return f2a(x, off);
}

__device__ __forceinline__ float4 rmax4(float4 v, float4* ws, int tid) {
    __syncthreads();
    int lane = tid & 31, wp = tid >> 5;
#pragma unroll
    for (int d = 16; d > 0; d >>= 1) {
        v.x = fmaxf(v.x, __shfl_xor_sync(0xffffffffu, v.x, d));
        v.y = fmaxf(v.y, __shfl_xor_sync(0xffffffffu, v.y, d));
        v.z = fmaxf(v.z, __shfl_xor_sync(0xffffffffu, v.z, d));
        v.w = fmaxf(v.w, __shfl_xor_sync(0xffffffffu, v.w, d));
    }
    if (lane == 0) ws[wp] = v;
    __syncthreads();
    if (wp == 0) {
        float4 t = (lane < 16) ? ws[lane]
                               : make_float4(-FLT_MAX, -FLT_MAX, -FLT_MAX, -FLT_MAX);
#pragma unroll
        for (int d = 8; d > 0; d >>= 1) {
            t.x = fmaxf(t.x, __shfl_xor_sync(0xffffffffu, t.x, d));
            t.y = fmaxf(t.y, __shfl_xor_sync(0xffffffffu, t.y, d));
            t.z = fmaxf(t.z, __shfl_xor_sync(0xffffffffu, t.z, d));
            t.w = fmaxf(t.w, __shfl_xor_sync(0xffffffffu, t.w, d));
        }
        if (lane == 0) ws[16] = t;
    }
    __syncthreads();
    return ws[16];
}

__device__ __forceinline__ float2 rmax2(float2 v, float2* ws, int tid) {
    __syncthreads();
    int lane = tid & 31, wp = tid >> 5;
#pragma unroll
    for (int d = 16; d > 0; d >>= 1) {
        v.x = fmaxf(v.x, __shfl_xor_sync(0xffffffffu, v.x, d));
        v.y = fmaxf(v.y, __shfl_xor_sync(0xffffffffu, v.y, d));
    }
    if (lane == 0) ws[wp] = v;
    __syncthreads();
    if (wp == 0) {
        float2 t = (lane < 16) ? ws[lane] : make_float2(-FLT_MAX, -FLT_MAX);
#pragma unroll
        for (int d = 8; d > 0; d >>= 1) {
            t.x = fmaxf(t.x, __shfl_xor_sync(0xffffffffu, t.x, d));
            t.y = fmaxf(t.y, __shfl_xor_sync(0xffffffffu, t.y, d));
        }
        if (lane == 0) ws[16] = t;
    }
    __syncthreads();
    return ws[16];
}

// pair-chained twiddle-and-store for forward DIF passes
#define TW_STORE_FWD(IDX_EXPR)                                            \
    {                                                                     \
        sf[IDX_EXPR(0)] = z[0];                                           \
        sf[IDX_EXPR(1)] = cmulf(z[8], tb);                                \
        const float2 t2 = cmulf(tb, tb);                                  \
        float2 cur = t2;                                                  \
        sf[IDX_EXPR(2)] = cmulf(z[rv[2]], cur);                           \
        sf[IDX_EXPR(3)] = cmulf(z[rv[3]], cmulf(cur, tb));                \
        _Pragma("unroll")                                                 \
        for (int q = 4; q < 16; q += 2) {                                 \
            cur = cmulf(cur, t2);                                         \
            sf[IDX_EXPR(q)] = cmulf(z[rv[q]], cur);                       \
            sf[IDX_EXPR(q + 1)] = cmulf(z[rv[q + 1]], cmulf(cur, tb));    \
        }                                                                 \
    }

// pair-chained input twiddles for inverse DIT passes: z[m] *= tbc^m
#define TW_APPLY_INV()                                                    \
    {                                                                     \
        z[1] = cmulf(z[1], tbc);                                          \
        const float2 t2 = cmulf(tbc, tbc);                                \
        float2 cur = t2;                                                  \
        z[2] = cmulf(z[2], cur);                                          \
        z[3] = cmulf(z[3], cmulf(cur, tbc));                              \
        _Pragma("unroll")                                                 \
        for (int m = 4; m < 16; m += 2) {                                 \
            cur = cmulf(cur, t2);                                         \
            z[m] = cmulf(z[m], cur);                                      \
            z[m + 1] = cmulf(z[m + 1], cmulf(cur, tbc));                  \
        }                                                                 \
    }

// ===================== fused kernel: one CTA per row pair =====================
// PROVEN FLOOR: 2 CTAs/SM (64 regs). occ-3 spills (round 14: 78us); do not retry.
__global__ void __launch_bounds__(NT, 2)
pipeline_kernel(const float* __restrict__ g_start, const float* __restrict__ g_end,
                const float* __restrict__ g_std,   const float* __restrict__ g_lb,
                const float* __restrict__ g_ub,    const int*   __restrict__ g_win,
                const float* __restrict__ g_scale, const float* __restrict__ g_noise,
                const float* __restrict__ g_omit,  const float* __restrict__ g_ppm,
                const float* __restrict__ g_range, float* __restrict__ out)
{
    extern __shared__ __align__(16) char smem_raw[];
    float*  scsA = (float*)smem_raw;                       // cumsum row A
    float*  scsB = (float*)(smem_raw + SCSB_OFF);          // cumsum row B
    float2* sw   = (float2*)(smem_raw + SW_OFF);           // smoothed signal
    float2* sf   = (float2*)smem_raw;                      // FFT buffer (aliases)
    float4* red  = (float4*)(smem_raw + RED_OFF);          // reduce scratch
    float2* redb = (float2*)(smem_raw + RED_OFF + 18 * 16);

    const int tid = threadIdx.x;
    const int g   = blockIdx.x;
    const int rA  = 2 * g, rB = 2 * g + 1;
    const int base = tid * SPT;
    const float inv_lm1 = 1.0f / (float)(LL - 1);
    const size_t raw_off = (size_t)NB * 2 * PP;
    const size_t ochA = ((size_t)rA * 2) * PP;
    const size_t ochB = ((size_t)rB * 2) * PP;
    const int rv[16] = {0, 8, 4, 12, 2, 10, 6, 14, 1, 9, 5, 13, 3, 11, 7, 15};

    // ---- out-of-band ch0 zero-fill up front: overlaps the entire pipeline ----
    {
        const float4 zz = make_float4(0.f, 0.f, 0.f, 0.f);
#pragma unroll
        for (int it = 0; it < 3; ++it) {
            int j = tid + it * NT;
            if (j < 1152) {
                int p4 = (j < 256) ? (j << 2) : (4608 + ((j - 256) << 2));
                __stcs((float4*)(out + raw_off + ochA + p4), zz);
                __stcs((float4*)(out + raw_off + ochB + p4), zz);
                __stcs((float4*)(out + ochA + (PP - 4 - p4)), zz);
                __stcs((float4*)(out + ochB + (PP - 4 - p4)), zz);
            }
        }
    }

    // ============== pipeline: both rows at once ==============
    const float sdA = g_std[rA], sdB = g_std[rB];
    float2 vv[SPT];
    {
        const float4* nzA = (const float4*)(g_noise + (size_t)rA * LL + base);
        const float4* nzB = (const float4*)(g_noise + (size_t)rB * LL + base);
        float4 a0 = __ldcs(nzA);
        float4 a1 = __ldcs(nzA + 1);
        float4 b0 = __ldcs(nzB);
        float4 b1 = __ldcs(nzB + 1);
        float ta[SPT] = {a0.x, a0.y, a0.z, a0.w, a1.x, a1.y, a1.z, a1.w};
        float tb[SPT] = {b0.x, b0.y, b0.z, b0.w, b1.x, b1.y, b1.z, b1.w};
        float aA = 0.f, aB = 0.f;
#pragma unroll
        for (int j = 0; j < SPT; ++j) {
            aA += sdA * (ta[j] - 0.5f);
            aB += sdB * (tb[j] - 0.5f);
            vv[j] = make_float2(aA, aB);
        }
    }
    float2 excl, r0, rl;
    {
        float2 incl = scan2_bc<true>(vv[SPT - 1], vv[0], (float2*)red, tid, &r0, &rl);
        excl = f2s(incl, vv[SPT - 1]);
    }

    // detrended deltas: compute ONCE, keep in vv
    float4 mx = make_float4(-FLT_MAX, -FLT_MAX, -FLT_MAX, -FLT_MAX);
#pragma unroll
    for (int j = 0; j < SPT; ++j) {
        float ft = (float)(base + j) * inv_lm1;
        float dA = (vv[j].x + excl.x) - (r0.x + (rl.x - r0.x) * ft);
        float dB = (vv[j].y + excl.y) - (r0.y + (rl.y - r0.y) * ft);
        vv[j] = make_float2(dA, dB);
        mx.x = fmaxf(mx.x, dA); mx.y = fmaxf(mx.y, -dA);
        mx.z = fmaxf(mx.z, dB); mx.w = fmaxf(mx.w, -dB);
    }
    float4 mm = rmax4(mx, red, tid);

    const float loA = g_lb[rA], hiA = g_ub[rA];
    const float loB = g_lb[rB], hiB = g_ub[rB];
    const float invdvA = 1.0f / fmaxf(1.0f, (mm.x + mm.y) / (hiA - loA));
    const float invdvB = 1.0f / fmaxf(1.0f, (mm.z + mm.w) / (hiB - loB));
    const float stA = g_start[rA], enA = g_end[rA];
    const float stB = g_start[rB], enB = g_end[rB];

    // squeeze + reflect + trend from the stored deltas; serial per-thread cumsum
    {
        float aA = 0.f, aB = 0.f;
#pragma unroll
        for (int j = 0; j < SPT; ++j) {
            float ft = (float)(base + j) * inv_lm1;
            {
                float d = vv[j].x * invdvA;
                float tr = stA + (enA - stA) * ft;
                float ub2 = hiA - tr, lb2 = loA - tr;
                float over = d - ub2;
                if (over >= 0.f) d = ub2 - over;
                float under = lb2 - d;
                if (under >= 0.f) d = lb2 + under;
                aA += tr + d;
            }
            {
                float d = vv[j].y * invdvB;
                float tr = stB + (enB - stB) * ft;
                float ub2 = hiB - tr, lb2 = loB - tr;
                float over = d - ub2;
                if (over >= 0.f) d = ub2 - over;
                float under = lb2 - d;
                if (under >= 0.f) d = lb2 + under;
                aB += tr + d;
            }
            vv[j] = make_float2(aA, aB);
        }
    }
    {
        float2 incl = scan2(vv[SPT - 1], (float2*)red, tid);
        float2 ex2 = f2s(incl, vv[SPT - 1]);
#pragma unroll
        for (int j = 0; j < SPT; ++j) {
            scsA[1 + base + j] = vv[j].x + ex2.x;
            scsB[1 + base + j] = vv[j].y + ex2.y;
        }
    }
    if (tid == 0) { scsA[0] = 0.f; scsB[0] = 0.f; }
    __syncthreads();

    const int wA = g_win[rA], wB = g_win[rB];
    const float invwA = 1.0f / (float)wA, invwB = 1.0f / (float)wB;
    const int whA = wA >> 1, whB = wB >> 1;
#pragma unroll
    for (int j = 0; j < SPT; ++j) {
        int t = base + j;
        int loa = max(t - whA, 0), hia = min(t - whA + wA, LL);
        int lob = max(t - whB, 0), hib = min(t - whB + wB, LL);
        float bA = (scsA[hia] - scsA[loa]) * invwA;
        float bB = (scsB[hib] - scsB[lob]) * invwB;
        vv[j] = make_float2(bA, bB);
    }
    if (tid == 0)      redb[0] = vv[0];
    if (tid == NT - 1) redb[1] = vv[SPT - 1];
    __syncthreads();
    const float2 b0v = redb[0], blv = redb[1];

    float2 ab = make_float2(0.f, 0.f);
#pragma unroll
    for (int j = 0; j < SPT; ++j) {
        float ft = (float)(base + j) * inv_lm1;
        float cA = vv[j].x - (b0v.x + (blv.x - b0v.x) * ft);
        float cB = vv[j].y - (b0v.y + (blv.y - b0v.y) * ft);
        vv[j] = make_float2(cA, cB);
        ab.x = fmaxf(ab.x, fabsf(cA));
        ab.y = fmaxf(ab.y, fabsf(cB));
    }
    float2 mr = rmax2(ab, (float2*)red, tid);
    const float facA = g_omit[rA] * g_scale[rA] / ((mr.x == 0.f) ? 1.0f : mr.x);
    const float facB = g_omit[rB] * g_scale[rB] / ((mr.y == 0.f) ? 1.0f : mr.y);
#pragma unroll
    for (int j = 0; j < SPT; ++j)
        sw[base + j] = make_float2(vv[j].x * facA, vv[j].y * facB);
    __syncthreads();

    // ============== fused interp + forward FFT pass A (sparse m=2..8) ==============
    float2 z[16];
#pragma unroll
    for (int m = 0; m < 16; ++m) z[m] = make_float2(0.f, 0.f);
    {
        const float rlo = g_range[0], rhi = g_range[1];
        const float istep = (float)(LL - 1) / (rhi - rlo);
        const float pstep = 12.0f / 8191.0f;   // ppm = linspace(-2, 10, 8192)
#pragma unroll
        for (int m = 2; m <= 8; ++m) {
            int p = tid + (m << 9);
            float xp = fmaf((float)p, pstep, -2.0f);
            float2 v = make_float2(0.f, 0.f);
            if (xp >= rlo && xp <= rhi) {
                float u = (xp - rlo) * istep;
                int i = (int)u;
                if (i > LL - 2) i = LL - 2;
                float f = u - (float)i;
                float2 s0 = sw[i], s1 = sw[i + 1];
                v.x = fmaf(s1.x - s0.x, f, s0.x);
                v.y = fmaf(s1.y - s0.y, f, s0.y);
            }
            z[m] = v;
            __stcs(out + ochA + (PP - 1 - p), v.x);
            __stcs(out + raw_off + ochA + p, v.x);
            __stcs(out + ochB + (PP - 1 - p), v.y);
            __stcs(out + raw_off + ochB + p, v.y);
        }
    }
    dft16_dif_sparse(z);
    {
        const int off = tid;
        float sn, cs;
        __sincosf(-7.66990393942820615e-4f * (float)off, &sn, &cs);  // -2pi/8192
        const float2 tb = make_float2(cs, sn);
        __syncthreads();   // all interp reads of sw complete before sf clobbers it
#define IDXA(q) PAD(((q) << 9) + off)
        TW_STORE_FWD(IDXA)
#undef IDXA
    }
    __syncthreads();   // cross-warp: pass A scatters into every warp's region

    // ---- forward pass B: radix-16, h=32 (warp-local region) ----
    {
        const int off = tid & 31;
        const int b0 = (tid >> 5) << 9;
        float2 zB[16];
#pragma unroll
        for (int m = 0; m < 16; ++m) zB[m] = sf[PAD(b0 + off + (m << 5))];
        float2* z = zB;
        dft16_dif<false>(z);
        float sn, cs;
        __sincosf(-1.22718463030851272e-2f * (float)off, &sn, &cs);  // -2pi/512
        const float2 tb = make_float2(cs, sn);
#define IDXB(q) PAD(b0 + ((q) << 5) + off)
        TW_STORE_FWD(IDXB)
#undef IDXB
    }
    __syncwarp();   // B -> middle is within the warp's own 512-region

    // ---- fused middle: fwd C (r16 h=2) + collapsed r2/Hilbert/r2 + inv C' ----
    {
        const int off = tid & 1;
        const int b0 = (tid >> 1) << 5;
        const float W32C = 0.98078528040323044913f, W32S = -0.19509032201612826785f;
        float2 z[16];
#pragma unroll
        for (int m = 0; m < 16; ++m) z[m] = sf[PAD(b0 + off + (m << 1))];
        dft16_dif<false>(z);
#pragma unroll
        for (int k = 0; k < 16; ++k) {
            z[k].x = __shfl_xor_sync(0xffffffffu, z[k].x, 1);
            z[k].y = __shfl_xor_sync(0xffffffffu, z[k].y, 1);
        }
        if (b0 == 0) z[0] = make_float2(0.f, 0.f);   // spectral positions p = 0, 1
#pragma unroll
        for (int k = 0; k < 16; ++k) z[k] = rotmi(z[k]);
        const float2 tb = make_float2(W32C, off ? -W32S : W32S);
        z[8] = cmulf(z[8], tb);
        {
            const float2 t2 = cmulf(tb, tb);
            float2 cur = t2;
            z[rv[2]] = cmulf(z[rv[2]], cur);
            z[rv[3]] = cmulf(z[rv[3]], cmulf(cur, tb));
#pragma unroll
            for (int q = 4; q < 16; q += 2) {
                cur = cmulf(cur, t2);
                z[rv[q]] = cmulf(z[rv[q]], cur);
                z[rv[q + 1]] = cmulf(z[rv[q + 1]], cmulf(cur, tb));
            }
        }
        dft16_dit<true>(z);
#pragma unroll
        for (int q = 0; q < 16; ++q) sf[PAD(b0 + off + (q << 1))] = z[q];
    }
    __syncwarp();   // middle -> B' is within the warp's own 512-region

    // ---- inverse pass B': radix-16 DIT, h=32 (warp-local) ----
    {
        const int off = tid & 31;
        const int b0 = (tid >> 5) << 9;
        float2 z[16];
#pragma unroll
        for (int m = 0; m < 16; ++m) z[m] = sf[PAD(b0 + off + (m << 5))];
        float sn, cs;
        __sincosf(-1.22718463030851272e-2f * (float)off, &sn, &cs);
        const float2 tbc = make_float2(cs, -sn);
        TW_APPLY_INV()
        dft16_dif<true>(z);
        sf[PAD(b0 + off)] = z[0];
#pragma unroll
        for (int q = 1; q < 16; ++q) sf[PAD(b0 + off + (q << 5))] = z[rv[q]];
    }
    __syncthreads();   // cross-warp: A' gathers stride-512

    // ---- inverse pass A': radix-16 DIT, h=512; write gmem directly ----
    {
        const int off = tid;
        float2 z[16];
#pragma unroll
        for (int m = 0; m < 16; ++m) z[m] = sf[PAD(off + (m << 9))];
        float sn, cs;
        __sincosf(-7.66990393942820615e-4f * (float)off, &sn, &cs);
        const float2 tbc = make_float2(cs, -sn);
        TW_APPLY_INV()
        dft16_dif<true>(z);
        const float invP = 1.0f / 4096.0f;   // 2/8192: middle sandwich factor folded in
        const size_t ch1a = ((size_t)rA * 2 + 1) * PP;
        const size_t ch1b = ((size_t)rB * 2 + 1) * PP;
#pragma unroll
        for (int q = 0; q < 16; ++q) {
            int p = off + (q << 9);
            float hA = z[rv[q]].x * invP;
            float hB = z[rv[q]].y * invP;
            __stcs(out + ch1a + (PP - 1 - p), hA);
            __stcs(out + raw_off + ch1a + p, hA);
            __stcs(out + ch1b + (PP - 1 - p), hB);
            __stcs(out + raw_off + ch1b + p, hB);
        }
    }
}

extern "C" void kernel_launch(void* const* d_in, const int* in_sizes, int n_in,
                              void* d_out, int out_size) {
    const float* g_start = (const float*)d_in[0];
    const float* g_end   = (const float*)d_in[1];
    const float* g_std   = (const float*)d_in[2];
    const float* g_lb    = (const float*)d_in[3];
    const float* g_ub    = (const float*)d_in[4];
    const int*   g_win   = (const int*)  d_in[5];
    const float* g_scale = (const float*)d_in[6];
    const float* g_noise = (const float*)d_in[7];
    const float* g_omit  = (const float*)d_in[8];
    const float* g_ppm   = (const float*)d_in[9];
    const float* g_range = (const float*)d_in[10];
    float* out = (float*)d_out;

    cudaFuncSetAttribute(pipeline_kernel,
                         cudaFuncAttributeMaxDynamicSharedMemorySize, SMEM_TOTAL);
    pipeline_kernel<<<NB / 2, NT, SMEM_TOTAL>>>(
        g_start, g_end, g_std, g_lb, g_ub, g_win, g_scale, g_noise,
        g_omit, g_ppm, g_range, out);
}

// round 16
// speedup vs baseline: 1.2991x; 1.0064x over previous
#include <cuda_runtime.h>
#include <math.h>
#include <float.h>

#define NB 1024   // batch
#define LL 4096   // simulated length
#define PP 8192   // acquired length
#define NT 512    // threads per CTA
#define SPT 8     // L elements per thread per row (LL / NT)
#define PAD(i) ((i) + ((i) >> 4))

// smem layout (dynamic), phases alias:
//   pipeline: scsA float[LL+1] at [0,16388); scsB float[LL+1] at [16400,32804)
//             sw  = float2[LL] at [36864, 69632)
//   FFT:      sf  = float2[8704] at [0, 69632)  (clobbers scsA/scsB/sw)
//   always:   red scratch at [69632, 70144)
#define SCSB_OFF   16400
#define SW_OFF     36864
#define RED_OFF    69632
#define SMEM_TOTAL (RED_OFF + 512)

__device__ __forceinline__ float2 cmulf(float2 a, float2 b) {
    return make_float2(a.x * b.x - a.y * b.y, a.x * b.y + a.y * b.x);
}
__device__ __forceinline__ float2 f2a(float2 a, float2 b) { return make_float2(a.x + b.x, a.y + b.y); }
__device__ __forceinline__ float2 f2s(float2 a, float2 b) { return make_float2(a.x - b.x, a.y - b.y); }
__device__ __forceinline__ float2 cmulc(float2 a, float c, float s) {
    return make_float2(a.x * c - a.y * s, a.x * s + a.y * c);
}
__device__ __forceinline__ float2 rotmi(float2 a) { return make_float2(a.y, -a.x); }  // *(−i)

// ===================== 16-point register DFTs =====================
template<bool INV>
__device__ __forceinline__ void dft16_dif(float2* z) {
    const float s = INV ? 1.0f : -1.0f;
    const float C1 = 0.92387953251128674f, S1 = 0.38268343236508978f, R2 = 0.70710678118654752f;
#define BF1(i0,i1) { float ax=z[i0].x-z[i1].x, ay=z[i0].y-z[i1].y; z[i0].x+=z[i1].x; z[i0].y+=z[i1].y; z[i1].x=ax; z[i1].y=ay; }
#define BFI(i0,i1) { float ax=z[i0].x-z[i1].x, ay=z[i0].y-z[i1].y; z[i0].x+=z[i1].x; z[i0].y+=z[i1].y; z[i1].x=-s*ay; z[i1].y=s*ax; }
#define BFT(i0,i1,tc,ts) { float ax=z[i0].x-z[i1].x, ay=z[i0].y-z[i1].y; z[i0].x+=z[i1].x; z[i0].y+=z[i1].y; z[i1].x=ax*(tc)-ay*(ts); z[i1].y=ax*(ts)+ay*(tc); }
    BF1(0, 8); BFT(1, 9, C1, s * S1); BFT(2, 10, R2, s * R2); BFT(3, 11, S1, s * C1);
    BFI(4, 12); BFT(5, 13, -S1, s * C1); BFT(6, 14, -R2, s * R2); BFT(7, 15, -C1, s * S1);
    BF1(0, 4); BFT(1, 5, R2, s * R2); BFI(2, 6); BFT(3, 7, -R2, s * R2);
    BF1(8, 12); BFT(9, 13, R2, s * R2); BFI(10, 14); BFT(11, 15, -R2, s * R2);
    BF1(0, 2); BFI(1, 3); BF1(4, 6); BFI(5, 7);
    BF1(8, 10); BFI(9, 11); BF1(12, 14); BFI(13, 15);
    BF1(0, 1); BF1(2, 3); BF1(4, 5); BF1(6, 7);
    BF1(8, 9); BF1(10, 11); BF1(12, 13); BF1(14, 15);
#undef BF1
#undef BFI
#undef BFT
}

// forward DIF16 specialized for inputs with z[0],z[1],z[9..15] == 0 (only z[2..8] live)
__device__ __forceinline__ void dft16_dif_sparse(float2* z) {
    const float C1 = 0.92387953251128674f, S1 = 0.38268343236508978f, R2 = 0.70710678118654752f;
    float2 y0 = z[8];
    float2 y8 = make_float2(-z[8].x, -z[8].y);
    float2 y2 = z[2], y10 = cmulc(z[2],  R2, -R2);
    float2 y3 = z[3], y11 = cmulc(z[3],  S1, -C1);
    float2 y4 = z[4], y12 = rotmi(z[4]);
    float2 y5 = z[5], y13 = cmulc(z[5], -S1, -C1);
    float2 y6 = z[6], y14 = cmulc(z[6], -R2, -R2);
    float2 y7 = z[7], y15 = cmulc(z[7], -C1, -S1);
    z[0] = f2a(y0, y4);   z[4]  = f2s(y0, y4);
    z[1] = y5;            z[5]  = cmulc(y5, -R2,  R2);
    z[2] = f2a(y2, y6);   z[6]  = rotmi(f2s(y2, y6));
    z[3] = f2a(y3, y7);   z[7]  = cmulc(f2s(y3, y7), -R2, -R2);
    z[8] = f2a(y8, y12);  z[12] = f2s(y8, y12);
    z[9] = y13;           z[13] = cmulc(y13, -R2,  R2);
    z[10] = f2a(y10, y14); z[14] = rotmi(f2s(y10, y14));
    z[11] = f2a(y11, y15); z[15] = cmulc(f2s(y11, y15), -R2, -R2);
#define BF1(i0,i1) { float ax=z[i0].x-z[i1].x, ay=z[i0].y-z[i1].y; z[i0].x+=z[i1].x; z[i0].y+=z[i1].y; z[i1].x=ax; z[i1].y=ay; }
#define BFIF(i0,i1) { float ax=z[i0].x-z[i1].x, ay=z[i0].y-z[i1].y; z[i0].x+=z[i1].x; z[i0].y+=z[i1].y; z[i1].x=ay; z[i1].y=-ax; }
    BF1(0, 2); BFIF(1, 3); BF1(4, 6); BFIF(5, 7);
    BF1(8, 10); BFIF(9, 11); BF1(12, 14); BFIF(13, 15);
    BF1(0, 1); BF1(2, 3); BF1(4, 5); BF1(6, 7);
    BF1(8, 9); BF1(10, 11); BF1(12, 13); BF1(14, 15);
#undef BF1
#undef BFIF
}

template<bool INV>
__device__ __forceinline__ void dft16_dit(float2* z) {
    const float s = INV ? 1.0f : -1.0f;
    const float C1 = 0.92387953251128674f, S1 = 0.38268343236508978f, R2 = 0.70710678118654752f;
#define BT1(i0,i1) { float bx=z[i1].x, by=z[i1].y; z[i1].x=z[i0].x-bx; z[i1].y=z[i0].y-by; z[i0].x+=bx; z[i0].y+=by; }
#define BTI(i0,i1) { float bx=-s*z[i1].y, by=s*z[i1].x; z[i1].x=z[i0].x-bx; z[i1].y=z[i0].y-by; z[i0].x+=bx; z[i0].y+=by; }
#define BTT(i0,i1,tc,ts) { float bx=z[i1].x*(tc)-z[i1].y*(ts), by=z[i1].x*(ts)+z[i1].y*(tc); z[i1].x=z[i0].x-bx; z[i1].y=z[i0].y-by; z[i0].x+=bx; z[i0].y+=by; }
    BT1(0, 1); BT1(2, 3); BT1(4, 5); BT1(6, 7);
    BT1(8, 9); BT1(10, 11); BT1(12, 13); BT1(14, 15);
    BT1(0, 2); BTI(1, 3); BT1(4, 6); BTI(5, 7);
    BT1(8, 10); BTI(9, 11); BT1(12, 14); BTI(13, 15);
    BT1(0, 4); BTT(1, 5, R2, s * R2); BTI(2, 6); BTT(3, 7, -R2, s * R2);
    BT1(8, 12); BTT(9, 13, R2, s * R2); BTI(10, 14); BTT(11, 15, -R2, s * R2);
    BT1(0, 8); BTT(1, 9, C1, s * S1); BTT(2, 10, R2, s * R2); BTT(3, 11, S1, s * C1);
    BTI(4, 12); BTT(5, 13, -S1, s * C1); BTT(6, 14, -R2, s * R2); BTT(7, 15, -C1, s * S1);
#undef BT1
#undef BTI
#undef BTT
}

// ===================== block helpers (512 threads = 16 warps) =====================
// FIRST=true skips the leading barrier (safe only when ws has no prior writer)
template<bool FIRST>
__device__ __forceinline__ float2 scan2_bc(float2 v, float2 v0, float2* ws, int tid,
                                           float2* r0_out, float2* tot_out) {
    if (!FIRST) __syncthreads();
    int lane = tid & 31, wp = tid >> 5;
    if (tid == 0) ws[17] = v0;
    float2 x = v;
#pragma unroll
    for (int d = 1; d < 32; d <<= 1) {
        float yx = __shfl_up_sync(0xffffffffu, x.x, d);
        float yy = __shfl_up_sync(0xffffffffu, x.y, d);
        if (lane >= d) { x.x += yx; x.y += yy; }
    }
    if (lane == 31) ws[wp] = x;
    __syncthreads();
    if (wp == 0) {
        float2 t = (lane < 16) ? ws[lane] : make_float2(0.f, 0.f);
#pragma unroll
        for (int d = 1; d < 16; d <<= 1) {
            float yx = __shfl_up_sync(0xffffffffu, t.x, d);
            float yy = __shfl_up_sync(0xffffffffu, t.y, d);
            if (lane >= d) { t.x += yx; t.y += yy; }
        }
        if (lane < 16) ws[lane] = t;
    }
    __syncthreads();
    float2 off = (wp > 0) ? ws[wp - 1] : make_float2(0.f, 0.f);
    *r0_out = ws[17];
    *tot_out = ws[15];
    return f2a(x, off);
}

__device__ __forceinline__ float2 scan2(float2 v, float2* ws, int tid) {
    __syncthreads();
    int lane = tid & 31, wp = tid >> 5;
    float2 x = v;
#pragma unroll
    for (int d = 1; d < 32; d <<= 1) {
        float yx = __shfl_up_sync(0xffffffffu, x.x, d);
        float yy = __shfl_up_sync(0xffffffffu, x.y, d);
        if (lane >= d) { x.x += yx; x.y += yy; }
    }
    if (lane == 31) ws[wp] = x;
    __syncthreads();
    if (wp == 0) {
        float2 t = (lane < 16) ? ws[lane] : make_float2(0.f, 0.f);
#pragma unroll
        for (int d = 1; d < 16; d <<= 1) {
            float yx = __shfl_up_sync(0xffffffffu, t.x, d);
            float yy = __shfl_up_sync(0xffffffffu, t.y, d);
            if (lane >= d) { t.x += yx; t.y += yy; }
        }
        if (lane < 16) ws[lane] = t;
    }
    __syncthreads();
    float2 off = (wp > 0) ? ws[wp - 1] : make_float2(0.f, 0.f);
    return f2a(x, off);
}

__device__ __forceinline__ float4 rmax4(float4 v, float4* ws, int tid) {
    __syncthreads();
    int lane = tid & 31, wp = tid >> 5;
#pragma unroll
    for (int d = 16; d > 0; d >>= 1) {
        v.x = fmaxf(v.x, __shfl_xor_sync(0xffffffffu, v.x, d));
        v.y = fmaxf(v.y, __shfl_xor_sync(0xffffffffu, v.y, d));
        v.z = fmaxf(v.z, __shfl_xor_sync(0xffffffffu, v.z, d));
        v.w = fmaxf(v.w, __shfl_xor_sync(0xffffffffu, v.w, d));
    }
    if (lane == 0) ws[wp] = v;
    __syncthreads();
    if (wp == 0) {
        float4 t = (lane < 16) ? ws[lane]
                               : make_float4(-FLT_MAX, -FLT_MAX, -FLT_MAX, -FLT_MAX);
#pragma unroll
        for (int d = 8; d > 0; d >>= 1) {
            t.x = fmaxf(t.x, __shfl_xor_sync(0xffffffffu, t.x, d));
            t.y = fmaxf(t.y, __shfl_xor_sync(0xffffffffu, t.y, d));
            t.z = fmaxf(t.z, __shfl_xor_sync(0xffffffffu, t.z, d));
            t.w = fmaxf(t.w, __shfl_xor_sync(0xffffffffu, t.w, d));
        }
        if (lane == 0) ws[16] = t;
    }
    __syncthreads();
    return ws[16];
}

__device__ __forceinline__ float2 rmax2(float2 v, float2* ws, int tid) {
    __syncthreads();
    int lane = tid & 31, wp = tid >> 5;
#pragma unroll
    for (int d = 16; d > 0; d >>= 1) {
        v.x = fmaxf(v.x, __shfl_xor_sync(0xffffffffu, v.x, d));
        v.y = fmaxf(v.y, __shfl_xor_sync(0xffffffffu, v.y, d));
    }
    if (lane == 0) ws[wp] = v;
    __syncthreads();
    if (wp == 0) {
        float2 t = (lane < 16) ? ws[lane] : make_float2(-FLT_MAX, -FLT_MAX);
#pragma unroll
        for (int d = 8; d > 0; d >>= 1) {
            t.x = fmaxf(t.x, __shfl_xor_sync(0xffffffffu, t.x, d));
            t.y = fmaxf(t.y, __shfl_xor_sync(0xffffffffu, t.y, d));
        }
        if (lane == 0) ws[16] = t;
    }
    __syncthreads();
    return ws[16];
}

// pair-chained twiddle-and-store for forward DIF passes
#define TW_STORE_FWD(IDX_EXPR)                                            \
    {                                                                     \
        sf[IDX_EXPR(0)] = z[0];                                           \
        sf[IDX_EXPR(1)] = cmulf(z[8], tb);                                \
        const float2 t2 = cmulf(tb, tb);                                  \
        float2 cur = t2;                                                  \
        sf[IDX_EXPR(2)] = cmulf(z[rv[2]], cur);                           \
        sf[IDX_EXPR(3)] = cmulf(z[rv[3]], cmulf(cur, tb));                \
        _Pragma("unroll")                                                 \
        for (int q = 4; q < 16; q += 2) {                                 \
            cur = cmulf(cur, t2);                                         \
            sf[IDX_EXPR(q)] = cmulf(z[rv[q]], cur);                       \
            sf[IDX_EXPR(q + 1)] = cmulf(z[rv[q + 1]], cmulf(cur, tb));    \
        }                                                                 \
    }

// pair-chained input twiddles for inverse DIT passes: z[m] *= tbc^m
#define TW_APPLY_INV()                                                    \
    {                                                                     \
        z[1] = cmulf(z[1], tbc);                                          \
        const float2 t2 = cmulf(tbc, tbc);                                \
        float2 cur = t2;                                                  \
        z[2] = cmulf(z[2], cur);                                          \
        z[3] = cmulf(z[3], cmulf(cur, tbc));                              \
        _Pragma("unroll")                                                 \
        for (int m = 4; m < 16; m += 2) {                                 \
            cur = cmulf(cur, t2);                                         \
            z[m] = cmulf(z[m], cur);                                      \
            z[m + 1] = cmulf(z[m + 1], cmulf(cur, tbc));                  \
        }                                                                 \
    }

// ===================== fused kernel: one CTA per row pair =====================
// PROVEN FLOOR: 2 CTAs/SM (64 regs). occ-3 spills (round 14: 78us); do not retry.
__global__ void __launch_bounds__(NT, 2)
pipeline_kernel(const float* __restrict__ g_start, const float* __restrict__ g_end,
                const float* __restrict__ g_std,   const float* __restrict__ g_lb,
                const float* __restrict__ g_ub,    const int*   __restrict__ g_win,
                const float* __restrict__ g_scale, const float* __restrict__ g_noise,
                const float* __restrict__ g_omit,  const float* __restrict__ g_ppm,
                const float* __restrict__ g_range, float* __restrict__ out)
{
    extern __shared__ __align__(16) char smem_raw[];
    float*  scsA = (float*)smem_raw;                       // cumsum row A
    float*  scsB = (float*)(smem_raw + SCSB_OFF);          // cumsum row B
    float2* sw   = (float2*)(smem_raw + SW_OFF);           // smoothed signal
    float2* sf   = (float2*)smem_raw;                      // FFT buffer (aliases)
    float4* red  = (float4*)(smem_raw + RED_OFF);          // reduce scratch

    const int tid = threadIdx.x;
    const int g   = blockIdx.x;
    const int rA  = 2 * g, rB = 2 * g + 1;
    const int base = tid * SPT;
    const float inv_lm1 = 1.0f / (float)(LL - 1);
    const size_t raw_off = (size_t)NB * 2 * PP;
    const size_t ochA = ((size_t)rA * 2) * PP;
    const size_t ochB = ((size_t)rB * 2) * PP;
    const int rv[16] = {0, 8, 4, 12, 2, 10, 6, 14, 1, 9, 5, 13, 3, 11, 7, 15};

    // ---- out-of-band ch0 zero-fill up front: overlaps the entire pipeline ----
    {
        const float4 zz = make_float4(0.f, 0.f, 0.f, 0.f);
#pragma unroll
        for (int it = 0; it < 3; ++it) {
            int j = tid + it * NT;
            if (j < 1152) {
                int p4 = (j < 256) ? (j << 2) : (4608 + ((j - 256) << 2));
                __stcs((float4*)(out + raw_off + ochA + p4), zz);
                __stcs((float4*)(out + raw_off + ochB + p4), zz);
                __stcs((float4*)(out + ochA + (PP - 4 - p4)), zz);
                __stcs((float4*)(out + ochB + (PP - 4 - p4)), zz);
            }
        }
    }

    // ============== pipeline: both rows at once ==============
    const float sdA = g_std[rA], sdB = g_std[rB];
    float2 vv[SPT];
    {
        const float4* nzA = (const float4*)(g_noise + (size_t)rA * LL + base);
        const float4* nzB = (const float4*)(g_noise + (size_t)rB * LL + base);
        float4 a0 = __ldcs(nzA);
        float4 a1 = __ldcs(nzA + 1);
        float4 b0 = __ldcs(nzB);
        float4 b1 = __ldcs(nzB + 1);
        float ta[SPT] = {a0.x, a0.y, a0.z, a0.w, a1.x, a1.y, a1.z, a1.w};
        float tb[SPT] = {b0.x, b0.y, b0.z, b0.w, b1.x, b1.y, b1.z, b1.w};
        float aA = 0.f, aB = 0.f;
#pragma unroll
        for (int j = 0; j < SPT; ++j) {
            aA += sdA * (ta[j] - 0.5f);
            aB += sdB * (tb[j] - 0.5f);
            vv[j] = make_float2(aA, aB);
        }
    }
    float2 excl, r0, rl;
    {
        float2 incl = scan2_bc<true>(vv[SPT - 1], vv[0], (float2*)red, tid, &r0, &rl);
        excl = f2s(incl, vv[SPT - 1]);
    }

    // detrended deltas: compute ONCE, keep in vv
    float4 mx = make_float4(-FLT_MAX, -FLT_MAX, -FLT_MAX, -FLT_MAX);
#pragma unroll
    for (int j = 0; j < SPT; ++j) {
        float ft = (float)(base + j) * inv_lm1;
        float dA = (vv[j].x + excl.x) - (r0.x + (rl.x - r0.x) * ft);
        float dB = (vv[j].y + excl.y) - (r0.y + (rl.y - r0.y) * ft);
        vv[j] = make_float2(dA, dB);
        mx.x = fmaxf(mx.x, dA); mx.y = fmaxf(mx.y, -dA);
        mx.z = fmaxf(mx.z, dB); mx.w = fmaxf(mx.w, -dB);
    }
    float4 mm = rmax4(mx, red, tid);

    const float loA = g_lb[rA], hiA = g_ub[rA];
    const float loB = g_lb[rB], hiB = g_ub[rB];
    const float invdvA = 1.0f / fmaxf(1.0f, (mm.x + mm.y) / (hiA - loA));
    const float invdvB = 1.0f / fmaxf(1.0f, (mm.z + mm.w) / (hiB - loB));
    const float stA = g_start[rA], enA = g_end[rA];
    const float stB = g_start[rB], enB = g_end[rB];

    // squeeze + reflect + trend from the stored deltas; serial per-thread cumsum
    {
        float aA = 0.f, aB = 0.f;
#pragma unroll
        for (int j = 0; j < SPT; ++j) {
            float ft = (float)(base + j) * inv_lm1;
            {
                float d = vv[j].x * invdvA;
                float tr = stA + (enA - stA) * ft;
                float ub2 = hiA - tr, lb2 = loA - tr;
                float over = d - ub2;
                if (over >= 0.f) d = ub2 - over;
                float under = lb2 - d;
                if (under >= 0.f) d = lb2 + under;
                aA += tr + d;
            }
            {
                float d = vv[j].y * invdvB;
                float tr = stB + (enB - stB) * ft;
                float ub2 = hiB - tr, lb2 = loB - tr;
                float over = d - ub2;
                if (over >= 0.f) d = ub2 - over;
                float under = lb2 - d;
                if (under >= 0.f) d = lb2 + under;
                aB += tr + d;
            }
            vv[j] = make_float2(aA, aB);
        }
    }
    {
        float2 incl = scan2(vv[SPT - 1], (float2*)red, tid);
        float2 ex2 = f2s(incl, vv[SPT - 1]);
#pragma unroll
        for (int j = 0; j < SPT; ++j) {
            scsA[1 + base + j] = vv[j].x + ex2.x;
            scsB[1 + base + j] = vv[j].y + ex2.y;
        }
    }
    if (tid == 0) { scsA[0] = 0.f; scsB[0] = 0.f; }
    __syncthreads();

    const int wA = g_win[rA], wB = g_win[rB];
    const float invwA = 1.0f / (float)wA, invwB = 1.0f / (float)wB;
    const int whA = wA >> 1, whB = wB >> 1;
#pragma unroll
    for (int j = 0; j < SPT; ++j) {
        int t = base + j;
        int loa = max(t - whA, 0), hia = min(t - whA + wA, LL);
        int lob = max(t - whB, 0), hib = min(t - whB + wB, LL);
        float bA = (scsA[hia] - scsA[loa]) * invwA;
        float bB = (scsB[hib] - scsB[lob]) * invwB;
        vv[j] = make_float2(bA, bB);
    }
    // b[0] and b[LL-1] computed redundantly by ALL threads from scs (broadcast
    // reads) — removes the redb write + one __syncthreads.
    const float2 b0v = make_float2((scsA[wA - whA] - scsA[0]) * invwA,
                                   (scsB[wB - whB] - scsB[0]) * invwB);
    const float2 blv = make_float2((scsA[LL] - scsA[LL - 1 - whA]) * invwA,
                                   (scsB[LL] - scsB[LL - 1 - whB]) * invwB);

    float2 ab = make_float2(0.f, 0.f);
#pragma unroll
    for (int j = 0; j < SPT; ++j) {
        float ft = (float)(base + j) * inv_lm1;
        float cA = vv[j].x - (b0v.x + (blv.x - b0v.x) * ft);
        float cB = vv[j].y - (b0v.y + (blv.y - b0v.y) * ft);
        vv[j] = make_float2(cA, cB);
        ab.x = fmaxf(ab.x, fabsf(cA));
        ab.y = fmaxf(ab.y, fabsf(cB));
    }
    float2 mr = rmax2(ab, (float2*)red, tid);
    const float facA = g_omit[rA] * g_scale[rA] / ((mr.x == 0.f) ? 1.0f : mr.x);
    const float facB = g_omit[rB] * g_scale[rB] / ((mr.y == 0.f) ? 1.0f : mr.y);
#pragma unroll
    for (int j = 0; j < SPT; ++j)
        sw[base + j] = make_float2(vv[j].x * facA, vv[j].y * facB);
    __syncthreads();

    // ============== fused interp + forward FFT pass A (sparse m=2..8) ==============
    float2 z[16];
#pragma unroll
    for (int m = 0; m < 16; ++m) z[m] = make_float2(0.f, 0.f);
    {
        const float rlo = g_range[0], rhi = g_range[1];
        const float istep = (float)(LL - 1) / (rhi - rlo);
        const float pstep = 12.0f / 8191.0f;   // ppm = linspace(-2, 10, 8192)
#pragma unroll
        for (int m = 2; m <= 8; ++m) {
            int p = tid + (m << 9);
            float xp = fmaf((float)p, pstep, -2.0f);
            float2 v = make_float2(0.f, 0.f);
            if (xp >= rlo && xp <= rhi) {
                float u = (xp - rlo) * istep;
                int i = (int)u;
                if (i > LL - 2) i = LL - 2;
                float f = u - (float)i;
                float2 s0 = sw[i], s1 = sw[i + 1];
                v.x = fmaf(s1.x - s0.x, f, s0.x);
                v.y = fmaf(s1.y - s0.y, f, s0.y);
            }
            z[m] = v;
            __stcs(out + ochA + (PP - 1 - p), v.x);
            __stcs(out + raw_off + ochA + p, v.x);
            __stcs(out + ochB + (PP - 1 - p), v.y);
            __stcs(out + raw_off + ochB + p, v.y);
        }
    }
    dft16_dif_sparse(z);
    {
        const int off = tid;
        float sn, cs;
        __sincosf(-7.66990393942820615e-4f * (float)off, &sn, &cs);  // -2pi/8192
        const float2 tb = make_float2(cs, sn);
        __syncthreads();   // all interp reads of sw complete before sf clobbers it
#define IDXA(q) PAD(((q) << 9) + off)
        TW_STORE_FWD(IDXA)
#undef IDXA
    }
    __syncthreads();   // cross-warp: pass A scatters into every warp's region

    // ---- forward pass B: radix-16, h=32 (warp-local region) ----
    {
        const int off = tid & 31;
        const int b0 = (tid >> 5) << 9;
        float2 zB[16];
#pragma unroll
        for (int m = 0; m < 16; ++m) zB[m] = sf[PAD(b0 + off + (m << 5))];
        float2* z = zB;
        dft16_dif<false>(z);
        float sn, cs;
        __sincosf(-1.22718463030851272e-2f * (float)off, &sn, &cs);  // -2pi/512
        const float2 tb = make_float2(cs, sn);
#define IDXB(q) PAD(b0 + ((q) << 5) + off)
        TW_STORE_FWD(IDXB)
#undef IDXB
    }
    __syncwarp();   // B -> middle is within the warp's own 512-region

    // ---- fused middle: fwd C (r16 h=2) + collapsed r2/Hilbert/r2 + inv C' ----
    {
        const int off = tid & 1;
        const int b0 = (tid >> 1) << 5;
        float2 z[16];
#pragma unroll
        for (int m = 0; m < 16; ++m) z[m] = sf[PAD(b0 + off + (m << 1))];
        dft16_dif<false>(z);
#pragma unroll
        for (int k = 0; k < 16; ++k) {
            z[k].x = __shfl_xor_sync(0xffffffffu, z[k].x, 1);
            z[k].y = __shfl_xor_sync(0xffffffffu, z[k].y, 1);
        }
        if (b0 == 0) z[0] = make_float2(0.f, 0.f);   // spectral positions p = 0, 1
#pragma unroll
        for (int k = 0; k < 16; ++k) z[k] = rotmi(z[k]);
        // combined twiddle W32^{±q}: all factors are compile-time constants,
        // only the sin sign depends on off — depth-1, fully parallel.
        {
            const float sgn = off ? -1.f : 1.f;
            const float TC[16] = {
                1.f,            0.98078528040323044913f,  0.92387953251128675613f,
                0.83146961230254523708f,  0.70710678118654752440f,  0.55557023301960222474f,
                0.38268343236508977173f,  0.19509032201612826785f,  0.f,
                -0.19509032201612826785f, -0.38268343236508977173f, -0.55557023301960222474f,
                -0.70710678118654752440f, -0.83146961230254523708f, -0.92387953251128675613f,
                -0.98078528040323044913f };
            const float TS[16] = {
                0.f,            -0.19509032201612826785f, -0.38268343236508977173f,
                -0.55557023301960222474f, -0.70710678118654752440f, -0.83146961230254523708f,
                -0.92387953251128675613f, -0.98078528040323044913f, -1.f,
                -0.98078528040323044913f, -0.92387953251128675613f, -0.83146961230254523708f,
                -0.70710678118654752440f, -0.55557023301960222474f, -0.38268343236508977173f,
                -0.19509032201612826785f };
#pragma unroll
            for (int q = 1; q < 16; ++q)
                z[rv[q]] = cmulc(z[rv[q]], TC[q], sgn * TS[q]);
        }
        dft16_dit<true>(z);
#pragma unroll
        for (int q = 0; q < 16; ++q) sf[PAD(b0 + off + (q << 1))] = z[q];
    }
    __syncwarp();   // middle -> B' is within the warp's own 512-region

    // ---- inverse pass B': radix-16 DIT, h=32 (warp-local) ----
    {
        const int off = tid & 31;
        const int b0 = (tid >> 5) << 9;
        float2 z[16];
#pragma unroll
        for (int m = 0; m < 16; ++m) z[m] = sf[PAD(b0 + off + (m << 5))];
        float sn, cs;
        __sincosf(-1.22718463030851272e-2f * (float)off, &sn, &cs);
        const float2 tbc = make_float2(cs, -sn);
        TW_APPLY_INV()
        dft16_dif<true>(z);
        sf[PAD(b0 + off)] = z[0];
#pragma unroll
        for (int q = 1; q < 16; ++q) sf[PAD(b0 + off + (q << 5))] = z[rv[q]];
    }
    __syncthreads();   // cross-warp: A' gathers stride-512

    // ---- inverse pass A': radix-16 DIT, h=512; write gmem directly ----
    {
        const int off = tid;
        float2 z[16];
#pragma unroll
        for (int m = 0; m < 16; ++m) z[m] = sf[PAD(off + (m << 9))];
        float sn, cs;
        __sincosf(-7.66990393942820615e-4f * (float)off, &sn, &cs);
        const float2 tbc = make_float2(cs, -sn);
        TW_APPLY_INV()
        dft16_dif<true>(z);
        const float invP = 1.0f / 4096.0f;   // 2/8192: middle sandwich factor folded in
        const size_t ch1a = ((size_t)rA * 2 + 1) * PP;
        const size_t ch1b = ((size_t)rB * 2 + 1) * PP;
#pragma unroll
        for (int q = 0; q < 16; ++q) {
            int p = off + (q << 9);
            float hA = z[rv[q]].x * invP;
            float hB = z[rv[q]].y * invP;
            __stcs(out + ch1a + (PP - 1 - p), hA);
            __stcs(out + raw_off + ch1a + p, hA);
            __stcs(out + ch1b + (PP - 1 - p), hB);
            __stcs(out + raw_off + ch1b + p, hB);
        }
    }
}

extern "C" void kernel_launch(void* const* d_in, const int* in_sizes, int n_in,
                              void* d_out, int out_size) {
    const float* g_start = (const float*)d_in[0];
    const float* g_end   = (const float*)d_in[1];
    const float* g_std   = (const float*)d_in[2];
    const float* g_lb    = (const float*)d_in[3];
    const float* g_ub    = (const float*)d_in[4];
    const int*   g_win   = (const int*)  d_in[5];
    const float* g_scale = (const float*)d_in[6];
    const float* g_noise = (const float*)d_in[7];
    const float* g_omit  = (const float*)d_in[8];
    const float* g_ppm   = (const float*)d_in[9];
    const float* g_range = (const float*)d_in[10];
    float* out = (float*)d_out;

    cudaFuncSetAttribute(pipeline_kernel,
                         cudaFuncAttributeMaxDynamicSharedMemorySize, SMEM_TOTAL);
    pipeline_kernel<<<NB / 2, NT, SMEM_TOTAL>>>(
        g_start, g_end, g_std, g_lb, g_ub, g_win, g_scale, g_noise,
        g_omit, g_ppm, g_range, out);
}

// round 17
// speedup vs baseline: 1.3046x; 1.0043x over previous
#include <cuda_runtime.h>
#include <math.h>
#include <float.h>

#define NB 1024   // batch
#define LL 4096   // simulated length
#define PP 8192   // acquired length
#define NT 512    // threads per CTA
#define SPT 8     // L elements per thread per row (LL / NT)
#define PAD(i) ((i) + ((i) >> 4))

// smem layout (dynamic), phases alias:
//   pipeline: scsA float[LL+1] at [0,16388); scsB float[LL+1] at [16400,32804)
//             sw  = float2[LL] at [36864, 69632)
//   FFT:      sf  = float2[8704] at [0, 69632)  (clobbers scsA/scsB/sw)
//   always:   red scratch at [69632, 70144)
#define SCSB_OFF   16400
#define SW_OFF     36864
#define RED_OFF    69632
#define SMEM_TOTAL (RED_OFF + 512)

__device__ __forceinline__ float2 cmulf(float2 a, float2 b) {
    return make_float2(a.x * b.x - a.y * b.y, a.x * b.y + a.y * b.x);
}
__device__ __forceinline__ float2 f2a(float2 a, float2 b) { return make_float2(a.x + b.x, a.y + b.y); }
__device__ __forceinline__ float2 f2s(float2 a, float2 b) { return make_float2(a.x - b.x, a.y - b.y); }
__device__ __forceinline__ float2 cmulc(float2 a, float c, float s) {
    return make_float2(a.x * c - a.y * s, a.x * s + a.y * c);
}
__device__ __forceinline__ float2 rotmi(float2 a) { return make_float2(a.y, -a.x); }  // *(−i)

// ===================== 16-point register DFTs =====================
template<bool INV>
__device__ __forceinline__ void dft16_dif(float2* z) {
    const float s = INV ? 1.0f : -1.0f;
    const float C1 = 0.92387953251128674f, S1 = 0.38268343236508978f, R2 = 0.70710678118654752f;
#define BF1(i0,i1) { float ax=z[i0].x-z[i1].x, ay=z[i0].y-z[i1].y; z[i0].x+=z[i1].x; z[i0].y+=z[i1].y; z[i1].x=ax; z[i1].y=ay; }
#define BFI(i0,i1) { float ax=z[i0].x-z[i1].x, ay=z[i0].y-z[i1].y; z[i0].x+=z[i1].x; z[i0].y+=z[i1].y; z[i1].x=-s*ay; z[i1].y=s*ax; }
#define BFT(i0,i1,tc,ts) { float ax=z[i0].x-z[i1].x, ay=z[i0].y-z[i1].y; z[i0].x+=z[i1].x; z[i0].y+=z[i1].y; z[i1].x=ax*(tc)-ay*(ts); z[i1].y=ax*(ts)+ay*(tc); }
    BF1(0, 8); BFT(1, 9, C1, s * S1); BFT(2, 10, R2, s * R2); BFT(3, 11, S1, s * C1);
    BFI(4, 12); BFT(5, 13, -S1, s * C1); BFT(6, 14, -R2, s * R2); BFT(7, 15, -C1, s * S1);
    BF1(0, 4); BFT(1, 5, R2, s * R2); BFI(2, 6); BFT(3, 7, -R2, s * R2);
    BF1(8, 12); BFT(9, 13, R2, s * R2); BFI(10, 14); BFT(11, 15, -R2, s * R2);
    BF1(0, 2); BFI(1, 3); BF1(4, 6); BFI(5, 7);
    BF1(8, 10); BFI(9, 11); BF1(12, 14); BFI(13, 15);
    BF1(0, 1); BF1(2, 3); BF1(4, 5); BF1(6, 7);
    BF1(8, 9); BF1(10, 11); BF1(12, 13); BF1(14, 15);
#undef BF1
#undef BFI
#undef BFT
}

// forward DIF16 specialized for inputs with z[0],z[1],z[9..15] == 0 (only z[2..8] live)
__device__ __forceinline__ void dft16_dif_sparse(float2* z) {
    const float C1 = 0.92387953251128674f, S1 = 0.38268343236508978f, R2 = 0.70710678118654752f;
    float2 y0 = z[8];
    float2 y8 = make_float2(-z[8].x, -z[8].y);
    float2 y2 = z[2], y10 = cmulc(z[2],  R2, -R2);
    float2 y3 = z[3], y11 = cmulc(z[3],  S1, -C1);
    float2 y4 = z[4], y12 = rotmi(z[4]);
    float2 y5 = z[5], y13 = cmulc(z[5], -S1, -C1);
    float2 y6 = z[6], y14 = cmulc(z[6], -R2, -R2);
    float2 y7 = z[7], y15 = cmulc(z[7], -C1, -S1);
    z[0] = f2a(y0, y4);   z[4]  = f2s(y0, y4);
    z[1] = y5;            z[5]  = cmulc(y5, -R2,  R2);
    z[2] = f2a(y2, y6);   z[6]  = rotmi(f2s(y2, y6));
    z[3] = f2a(y3, y7);   z[7]  = cmulc(f2s(y3, y7), -R2, -R2);
    z[8] = f2a(y8, y12);  z[12] = f2s(y8, y12);
    z[9] = y13;           z[13] = cmulc(y13, -R2,  R2);
    z[10] = f2a(y10, y14); z[14] = rotmi(f2s(y10, y14));
    z[11] = f2a(y11, y15); z[15] = cmulc(f2s(y11, y15), -R2, -R2);
#define BF1(i0,i1) { float ax=z[i0].x-z[i1].x, ay=z[i0].y-z[i1].y; z[i0].x+=z[i1].x; z[i0].y+=z[i1].y; z[i1].x=ax; z[i1].y=ay; }
#define BFIF(i0,i1) { float ax=z[i0].x-z[i1].x, ay=z[i0].y-z[i1].y; z[i0].x+=z[i1].x; z[i0].y+=z[i1].y; z[i1].x=ay; z[i1].y=-ax; }
    BF1(0, 2); BFIF(1, 3); BF1(4, 6); BFIF(5, 7);
    BF1(8, 10); BFIF(9, 11); BF1(12, 14); BFIF(13, 15);
    BF1(0, 1); BF1(2, 3); BF1(4, 5); BF1(6, 7);
    BF1(8, 9); BF1(10, 11); BF1(12, 13); BF1(14, 15);
#undef BF1
#undef BFIF
}

template<bool INV>
__device__ __forceinline__ void dft16_dit(float2* z) {
    const float s = INV ? 1.0f : -1.0f;
    const float C1 = 0.92387953251128674f, S1 = 0.38268343236508978f, R2 = 0.70710678118654752f;
#define BT1(i0,i1) { float bx=z[i1].x, by=z[i1].y; z[i1].x=z[i0].x-bx; z[i1].y=z[i0].y-by; z[i0].x+=bx; z[i0].y+=by; }
#define BTI(i0,i1) { float bx=-s*z[i1].y, by=s*z[i1].x; z[i1].x=z[i0].x-bx; z[i1].y=z[i0].y-by; z[i0].x+=bx; z[i0].y+=by; }
#define BTT(i0,i1,tc,ts) { float bx=z[i1].x*(tc)-z[i1].y*(ts), by=z[i1].x*(ts)+z[i1].y*(tc); z[i1].x=z[i0].x-bx; z[i1].y=z[i0].y-by; z[i0].x+=bx; z[i0].y+=by; }
    BT1(0, 1); BT1(2, 3); BT1(4, 5); BT1(6, 7);
    BT1(8, 9); BT1(10, 11); BT1(12, 13); BT1(14, 15);
    BT1(0, 2); BTI(1, 3); BT1(4, 6); BTI(5, 7);
    BT1(8, 10); BTI(9, 11); BT1(12, 14); BTI(13, 15);
    BT1(0, 4); BTT(1, 5, R2, s * R2); BTI(2, 6); BTT(3, 7, -R2, s * R2);
    BT1(8, 12); BTT(9, 13, R2, s * R2); BTI(10, 14); BTT(11, 15, -R2, s * R2);
    BT1(0, 8); BTT(1, 9, C1, s * S1); BTT(2, 10, R2, s * R2); BTT(3, 11, S1, s * C1);
    BTI(4, 12); BTT(5, 13, -S1, s * C1); BTT(6, 14, -R2, s * R2); BTT(7, 15, -C1, s * S1);
#undef BT1
#undef BTI
#undef BTT
}

// ===================== block helpers (512 threads = 16 warps) =====================
// FIRST=true skips the leading barrier (safe only when ws has no prior writer)
template<bool FIRST>
__device__ __forceinline__ float2 scan2_bc(float2 v, float2 v0, float2* ws, int tid,
                                           float2* r0_out, float2* tot_out) {
    if (!FIRST) __syncthreads();
    int lane = tid & 31, wp = tid >> 5;
    if (tid == 0) ws[17] = v0;
    float2 x = v;
#pragma unroll
    for (int d = 1; d < 32; d <<= 1) {
        float yx = __shfl_up_sync(0xffffffffu, x.x, d);
        float yy = __shfl_up_sync(0xffffffffu, x.y, d);
        if (lane >= d) { x.x += yx; x.y += yy; }
    }
    if (lane == 31) ws[wp] = x;
    __syncthreads();
    if (wp == 0) {
        float2 t = (lane < 16) ? ws[lane] : make_float2(0.f, 0.f);
#pragma unroll
        for (int d = 1; d < 16; d <<= 1) {
            float yx = __shfl_up_sync(0xffffffffu, t.x, d);
            float yy = __shfl_up_sync(0xffffffffu, t.y, d);
            if (lane >= d) { t.x += yx; t.y += yy; }
        }
        if (lane < 16) ws[lane] = t;
    }
    __syncthreads();
    float2 off = (wp > 0) ? ws[wp - 1] : make_float2(0.f, 0.f);
    *r0_out = ws[17];
    *tot_out = ws[15];
    return f2a(x, off);
}

__device__ __forceinline__ float2 scan2(float2 v, float2* ws, int tid) {
    __syncthreads();
    int lane = tid & 31, wp = tid >> 5;
    float2 x = v;
#pragma unroll
    for (int d = 1; d < 32; d <<= 1) {
        float yx = __shfl_up_sync(0xffffffffu, x.x, d);
        float yy = __shfl_up_sync(0xffffffffu, x.y, d);
        if (lane >= d) { x.x += yx; x.y += yy; }
    }
    if (lane == 31) ws[wp] = x;
    __syncthreads();
    if (wp == 0) {
        float2 t = (lane < 16) ? ws[lane] : make_float2(0.f, 0.f);
#pragma unroll
        for (int d = 1; d < 16; d <<= 1) {
            float yx = __shfl_up_sync(0xffffffffu, t.x, d);
            float yy = __shfl_up_sync(0xffffffffu, t.y, d);
            if (lane >= d) { t.x += yx; t.y += yy; }
        }
        if (lane < 16) ws[lane] = t;
    }
    __syncthreads();
    float2 off = (wp > 0) ? ws[wp - 1] : make_float2(0.f, 0.f);
    return f2a(x, off);
}

__device__ __forceinline__ float4 rmax4(float4 v, float4* ws, int tid) {
    __syncthreads();
    int lane = tid & 31, wp = tid >> 5;
#pragma unroll
    for (int d = 16; d > 0; d >>= 1) {
        v.x = fmaxf(v.x, __shfl_xor_sync(0xffffffffu, v.x, d));
        v.y = fmaxf(v.y, __shfl_xor_sync(0xffffffffu, v.y, d));
        v.z = fmaxf(v.z, __shfl_xor_sync(0xffffffffu, v.z, d));
        v.w = fmaxf(v.w, __shfl_xor_sync(0xffffffffu, v.w, d));
    }
    if (lane == 0) ws[wp] = v;
    __syncthreads();
    if (wp == 0) {
        float4 t = (lane < 16) ? ws[lane]
                               : make_float4(-FLT_MAX, -FLT_MAX, -FLT_MAX, -FLT_MAX);
#pragma unroll
        for (int d = 8; d > 0; d >>= 1) {
            t.x = fmaxf(t.x, __shfl_xor_sync(0xffffffffu, t.x, d));
            t.y = fmaxf(t.y, __shfl_xor_sync(0xffffffffu, t.y, d));
            t.z = fmaxf(t.z, __shfl_xor_sync(0xffffffffu, t.z, d));
            t.w = fmaxf(t.w, __shfl_xor_sync(0xffffffffu, t.w, d));
        }
        if (lane == 0) ws[16] = t;
    }
    __syncthreads();
    return ws[16];
}

__device__ __forceinline__ float2 rmax2(float2 v, float2* ws, int tid) {
    __syncthreads();
    int lane = tid & 31, wp = tid >> 5;
#pragma unroll
    for (int d = 16; d > 0; d >>= 1) {
        v.x = fmaxf(v.x, __shfl_xor_sync(0xffffffffu, v.x, d));
        v.y = fmaxf(v.y, __shfl_xor_sync(0xffffffffu, v.y, d));
    }
    if (lane == 0) ws[wp] = v;
    __syncthreads();
    if (wp == 0) {
        float2 t = (lane < 16) ? ws[lane] : make_float2(-FLT_MAX, -FLT_MAX);
#pragma unroll
        for (int d = 8; d > 0; d >>= 1) {
            t.x = fmaxf(t.x, __shfl_xor_sync(0xffffffffu, t.x, d));
            t.y = fmaxf(t.y, __shfl_xor_sync(0xffffffffu, t.y, d));
        }
        if (lane == 0) ws[16] = t;
    }
    __syncthreads();
    return ws[16];
}

// pair-chained twiddle-and-store for forward DIF passes
#define TW_STORE_FWD(IDX_EXPR)                                            \
    {                                                                     \
        sf[IDX_EXPR(0)] = z[0];                                           \
        sf[IDX_EXPR(1)] = cmulf(z[8], tb);                                \
        const float2 t2 = cmulf(tb, tb);                                  \
        float2 cur = t2;                                                  \
        sf[IDX_EXPR(2)] = cmulf(z[rv[2]], cur);                           \
        sf[IDX_EXPR(3)] = cmulf(z[rv[3]], cmulf(cur, tb));                \
        _Pragma("unroll")                                                 \
        for (int q = 4; q < 16; q += 2) {                                 \
            cur = cmulf(cur, t2);                                         \
            sf[IDX_EXPR(q)] = cmulf(z[rv[q]], cur);                       \
            sf[IDX_EXPR(q + 1)] = cmulf(z[rv[q + 1]], cmulf(cur, tb));    \
        }                                                                 \
    }

// pair-chained input twiddles for inverse DIT passes: z[m] *= tbc^m
#define TW_APPLY_INV()                                                    \
    {                                                                     \
        z[1] = cmulf(z[1], tbc);                                          \
        const float2 t2 = cmulf(tbc, tbc);                                \
        float2 cur = t2;                                                  \
        z[2] = cmulf(z[2], cur);                                          \
        z[3] = cmulf(z[3], cmulf(cur, tbc));                              \
        _Pragma("unroll")                                                 \
        for (int m = 4; m < 16; m += 2) {                                 \
            cur = cmulf(cur, t2);                                         \
            z[m] = cmulf(z[m], cur);                                      \
            z[m + 1] = cmulf(z[m + 1], cmulf(cur, tbc));                  \
        }                                                                 \
    }

// ===================== fused kernel: one CTA per row pair =====================
// PROVEN FLOOR: 2 CTAs/SM (64 regs). occ-3 spills (round 14: 78us); do not retry.
__global__ void __launch_bounds__(NT, 2)
pipeline_kernel(const float* __restrict__ g_start, const float* __restrict__ g_end,
                const float* __restrict__ g_std,   const float* __restrict__ g_lb,
                const float* __restrict__ g_ub,    const int*   __restrict__ g_win,
                const float* __restrict__ g_scale, const float* __restrict__ g_noise,
                const float* __restrict__ g_omit,  const float* __restrict__ g_ppm,
                const float* __restrict__ g_range, float* __restrict__ out)
{
    extern __shared__ __align__(16) char smem_raw[];
    float*  scsA = (float*)smem_raw;                       // cumsum row A
    float*  scsB = (float*)(smem_raw + SCSB_OFF);          // cumsum row B
    float2* sw   = (float2*)(smem_raw + SW_OFF);           // smoothed signal
    float2* sf   = (float2*)smem_raw;                      // FFT buffer (aliases)
    float4* red  = (float4*)(smem_raw + RED_OFF);          // reduce scratch

    const int tid = threadIdx.x;
    const int g   = blockIdx.x;
    const int rA  = 2 * g, rB = 2 * g + 1;
    const int base = tid * SPT;
    const float inv_lm1 = 1.0f / (float)(LL - 1);
    const size_t raw_off = (size_t)NB * 2 * PP;
    const size_t ochA = ((size_t)rA * 2) * PP;
    const size_t ochB = ((size_t)rB * 2) * PP;
    const int rv[16] = {0, 8, 4, 12, 2, 10, 6, 14, 1, 9, 5, 13, 3, 11, 7, 15};

    // ---- out-of-band ch0 zero-fill up front: overlaps the entire pipeline ----
    {
        const float4 zz = make_float4(0.f, 0.f, 0.f, 0.f);
        // iterations 0 and 1 are always in range (j = tid, tid+512 < 1152)
#pragma unroll
        for (int it = 0; it < 2; ++it) {
            int j = tid + it * NT;
            int p4 = (j < 256) ? (j << 2) : (4608 + ((j - 256) << 2));
            __stcs((float4*)(out + raw_off + ochA + p4), zz);
            __stcs((float4*)(out + raw_off + ochB + p4), zz);
            __stcs((float4*)(out + ochA + (PP - 4 - p4)), zz);
            __stcs((float4*)(out + ochB + (PP - 4 - p4)), zz);
        }
        if (tid < 128) {   // iteration 2: j = tid + 1024 in [1024, 1152)
            int p4 = 4608 + ((tid + 768) << 2);
            __stcs((float4*)(out + raw_off + ochA + p4), zz);
            __stcs((float4*)(out + raw_off + ochB + p4), zz);
            __stcs((float4*)(out + ochA + (PP - 4 - p4)), zz);
            __stcs((float4*)(out + ochB + (PP - 4 - p4)), zz);
        }
    }

    // ============== pipeline: both rows at once ==============
    const float sdA = g_std[rA], sdB = g_std[rB];
    float2 vv[SPT];
    {
        const float4* nzA = (const float4*)(g_noise + (size_t)rA * LL + base);
        const float4* nzB = (const float4*)(g_noise + (size_t)rB * LL + base);
        float4 a0 = __ldcs(nzA);
        float4 a1 = __ldcs(nzA + 1);
        float4 b0 = __ldcs(nzB);
        float4 b1 = __ldcs(nzB + 1);
        float ta[SPT] = {a0.x, a0.y, a0.z, a0.w, a1.x, a1.y, a1.z, a1.w};
        float tb[SPT] = {b0.x, b0.y, b0.z, b0.w, b1.x, b1.y, b1.z, b1.w};
        float aA = 0.f, aB = 0.f;
#pragma unroll
        for (int j = 0; j < SPT; ++j) {
            aA += sdA * (ta[j] - 0.5f);
            aB += sdB * (tb[j] - 0.5f);
            vv[j] = make_float2(aA, aB);
        }
    }
    float2 excl, r0, rl;
    {
        float2 incl = scan2_bc<true>(vv[SPT - 1], vv[0], (float2*)red, tid, &r0, &rl);
        excl = f2s(incl, vv[SPT - 1]);
    }

    // detrended deltas: compute ONCE, keep in vv
    float4 mx = make_float4(-FLT_MAX, -FLT_MAX, -FLT_MAX, -FLT_MAX);
#pragma unroll
    for (int j = 0; j < SPT; ++j) {
        float ft = (float)(base + j) * inv_lm1;
        float dA = (vv[j].x + excl.x) - (r0.x + (rl.x - r0.x) * ft);
        float dB = (vv[j].y + excl.y) - (r0.y + (rl.y - r0.y) * ft);
        vv[j] = make_float2(dA, dB);
        mx.x = fmaxf(mx.x, dA); mx.y = fmaxf(mx.y, -dA);
        mx.z = fmaxf(mx.z, dB); mx.w = fmaxf(mx.w, -dB);
    }
    float4 mm = rmax4(mx, red, tid);

    const float loA = g_lb[rA], hiA = g_ub[rA];
    const float loB = g_lb[rB], hiB = g_ub[rB];
    const float invdvA = 1.0f / fmaxf(1.0f, (mm.x + mm.y) / (hiA - loA));
    const float invdvB = 1.0f / fmaxf(1.0f, (mm.z + mm.w) / (hiB - loB));
    const float stA = g_start[rA], enA = g_end[rA];
    const float stB = g_start[rB], enB = g_end[rB];

    // squeeze + reflect + trend from the stored deltas; serial per-thread cumsum
    {
        float aA = 0.f, aB = 0.f;
#pragma unroll
        for (int j = 0; j < SPT; ++j) {
            float ft = (float)(base + j) * inv_lm1;
            {
                float d = vv[j].x * invdvA;
                float tr = stA + (enA - stA) * ft;
                float ub2 = hiA - tr, lb2 = loA - tr;
                float over = d - ub2;
                if (over >= 0.f) d = ub2 - over;
                float under = lb2 - d;
                if (under >= 0.f) d = lb2 + under;
                aA += tr + d;
            }
            {
                float d = vv[j].y * invdvB;
                float tr = stB + (enB - stB) * ft;
                float ub2 = hiB - tr, lb2 = loB - tr;
                float over = d - ub2;
                if (over >= 0.f) d = ub2 - over;
                float under = lb2 - d;
                if (under >= 0.f) d = lb2 + under;
                aB += tr + d;
            }
            vv[j] = make_float2(aA, aB);
        }
    }
    {
        float2 incl = scan2(vv[SPT - 1], (float2*)red, tid);
        float2 ex2 = f2s(incl, vv[SPT - 1]);
#pragma unroll
        for (int j = 0; j < SPT; ++j) {
            scsA[1 + base + j] = vv[j].x + ex2.x;
            scsB[1 + base + j] = vv[j].y + ex2.y;
        }
    }
    if (tid == 0) { scsA[0] = 0.f; scsB[0] = 0.f; }
    __syncthreads();

    const int wA = g_win[rA], wB = g_win[rB];
    const float invwA = 1.0f / (float)wA, invwB = 1.0f / (float)wB;
    const int whA = wA >> 1, whB = wB >> 1;
#pragma unroll
    for (int j = 0; j < SPT; ++j) {
        int t = base + j;
        int loa = max(t - whA, 0), hia = min(t - whA + wA, LL);
        int lob = max(t - whB, 0), hib = min(t - whB + wB, LL);
        float bA = (scsA[hia] - scsA[loa]) * invwA;
        float bB = (scsB[hib] - scsB[lob]) * invwB;
        vv[j] = make_float2(bA, bB);
    }
    // b[0] and b[LL-1] computed redundantly by ALL threads (broadcast reads)
    const float2 b0v = make_float2((scsA[wA - whA] - scsA[0]) * invwA,
                                   (scsB[wB - whB] - scsB[0]) * invwB);
    const float2 blv = make_float2((scsA[LL] - scsA[LL - 1 - whA]) * invwA,
                                   (scsB[LL] - scsB[LL - 1 - whB]) * invwB);

    float2 ab = make_float2(0.f, 0.f);
#pragma unroll
    for (int j = 0; j < SPT; ++j) {
        float ft = (float)(base + j) * inv_lm1;
        float cA = vv[j].x - (b0v.x + (blv.x - b0v.x) * ft);
        float cB = vv[j].y - (b0v.y + (blv.y - b0v.y) * ft);
        vv[j] = make_float2(cA, cB);
        ab.x = fmaxf(ab.x, fabsf(cA));
        ab.y = fmaxf(ab.y, fabsf(cB));
    }
    float2 mr = rmax2(ab, (float2*)red, tid);
    const float facA = g_omit[rA] * g_scale[rA] / ((mr.x == 0.f) ? 1.0f : mr.x);
    const float facB = g_omit[rB] * g_scale[rB] / ((mr.y == 0.f) ? 1.0f : mr.y);
#pragma unroll
    for (int j = 0; j < SPT; ++j)
        sw[base + j] = make_float2(vv[j].x * facA, vv[j].y * facB);
    __syncthreads();

    // ============== fused interp + forward FFT pass A (sparse m=2..8) ==============
    float2 z[16];
#pragma unroll
    for (int m = 0; m < 16; ++m) z[m] = make_float2(0.f, 0.f);
    {
        const float rlo = g_range[0], rhi = g_range[1];
        const float istep = (float)(LL - 1) / (rhi - rlo);
        const float pstep = 12.0f / 8191.0f;   // ppm = linspace(-2, 10, 8192)
#pragma unroll
        for (int m = 2; m <= 8; ++m) {
            int p = tid + (m << 9);
            float xp = fmaf((float)p, pstep, -2.0f);
            float2 v = make_float2(0.f, 0.f);
            if (xp >= rlo && xp <= rhi) {
                float u = (xp - rlo) * istep;
                int i = (int)u;
                if (i > LL - 2) i = LL - 2;
                float f = u - (float)i;
                float2 s0 = sw[i], s1 = sw[i + 1];
                v.x = fmaf(s1.x - s0.x, f, s0.x);
                v.y = fmaf(s1.y - s0.y, f, s0.y);
            }
            z[m] = v;
            __stcs(out + ochA + (PP - 1 - p), v.x);
            __stcs(out + raw_off + ochA + p, v.x);
            __stcs(out + ochB + (PP - 1 - p), v.y);
            __stcs(out + raw_off + ochB + p, v.y);
        }
    }
    dft16_dif_sparse(z);
    {
        const int off = tid;
        float sn, cs;
        __sincosf(-7.66990393942820615e-4f * (float)off, &sn, &cs);  // -2pi/8192
        const float2 tb = make_float2(cs, sn);
        __syncthreads();   // all interp reads of sw complete before sf clobbers it
#define IDXA(q) PAD(((q) << 9) + off)
        TW_STORE_FWD(IDXA)
#undef IDXA
    }
    __syncthreads();   // cross-warp: pass A scatters into every warp's region

    // ---- forward pass B: radix-16, h=32 (warp-local region) ----
    {
        const int off = tid & 31;
        const int b0 = (tid >> 5) << 9;
        float2 zB[16];
#pragma unroll
        for (int m = 0; m < 16; ++m) zB[m] = sf[PAD(b0 + off + (m << 5))];
        float2* z = zB;
        dft16_dif<false>(z);
        float sn, cs;
        __sincosf(-1.22718463030851272e-2f * (float)off, &sn, &cs);  // -2pi/512
        const float2 tb = make_float2(cs, sn);
#define IDXB(q) PAD(b0 + ((q) << 5) + off)
        TW_STORE_FWD(IDXB)
#undef IDXB
    }
    __syncwarp();   // B -> middle is within the warp's own 512-region

    // ---- fused middle: fwd C (r16 h=2) + collapsed r2/Hilbert/r2 + inv C' ----
    {
        const int off = tid & 1;
        const int b0 = (tid >> 1) << 5;
        float2 z[16];
#pragma unroll
        for (int m = 0; m < 16; ++m) z[m] = sf[PAD(b0 + off + (m << 1))];
        dft16_dif<false>(z);
#pragma unroll
        for (int k = 0; k < 16; ++k) {
            z[k].x = __shfl_xor_sync(0xffffffffu, z[k].x, 1);
            z[k].y = __shfl_xor_sync(0xffffffffu, z[k].y, 1);
        }
        if (b0 == 0) z[0] = make_float2(0.f, 0.f);   // spectral positions p = 0, 1
#pragma unroll
        for (int k = 0; k < 16; ++k) z[k] = rotmi(z[k]);
        // combined twiddle W32^{±q}: compile-time constants, depth-1 parallel
        {
            const float sgn = off ? -1.f : 1.f;
            const float TC[16] = {
                1.f,            0.98078528040323044913f,  0.92387953251128675613f,
                0.83146961230254523708f,  0.70710678118654752440f,  0.55557023301960222474f,
                0.38268343236508977173f,  0.19509032201612826785f,  0.f,
                -0.19509032201612826785f, -0.38268343236508977173f, -0.55557023301960222474f,
                -0.70710678118654752440f, -0.83146961230254523708f, -0.92387953251128675613f,
                -0.98078528040323044913f };
            const float TS[16] = {
                0.f,            -0.19509032201612826785f, -0.38268343236508977173f,
                -0.55557023301960222474f, -0.70710678118654752440f, -0.83146961230254523708f,
                -0.92387953251128675613f, -0.98078528040323044913f, -1.f,
                -0.98078528040323044913f, -0.92387953251128675613f, -0.83146961230254523708f,
                -0.70710678118654752440f, -0.55557023301960222474f, -0.38268343236508977173f,
                -0.19509032201612826785f };
#pragma unroll
            for (int q = 1; q < 16; ++q)
                z[rv[q]] = cmulc(z[rv[q]], TC[q], sgn * TS[q]);
        }
        dft16_dit<true>(z);
#pragma unroll
        for (int q = 0; q < 16; ++q) sf[PAD(b0 + off + (q << 1))] = z[q];
    }
    __syncwarp();   // middle -> B' is within the warp's own 512-region

    // ---- inverse pass B': radix-16 DIT, h=32 (warp-local) ----
    {
        const int off = tid & 31;
        const int b0 = (tid >> 5) << 9;
        float2 z[16];
#pragma unroll
        for (int m = 0; m < 16; ++m) z[m] = sf[PAD(b0 + off + (m << 5))];
        float sn, cs;
        __sincosf(-1.22718463030851272e-2f * (float)off, &sn, &cs);
        const float2 tbc = make_float2(cs, -sn);
        TW_APPLY_INV()
        dft16_dif<true>(z);
        sf[PAD(b0 + off)] = z[0];
#pragma unroll
        for (int q = 1; q < 16; ++q) sf[PAD(b0 + off + (q << 5))] = z[rv[q]];
    }
    __syncthreads();   // cross-warp: A' gathers stride-512

    // ---- inverse pass A': radix-16 DIT, h=512; write gmem directly ----
    {
        const int off = tid;
        float2 z[16];
#pragma unroll
        for (int m = 0; m < 16; ++m) z[m] = sf[PAD(off + (m << 9))];
        float sn, cs;
        __sincosf(-7.66990393942820615e-4f * (float)off, &sn, &cs);
        const float2 tbc = make_float2(cs, -sn);
        TW_APPLY_INV()
        dft16_dif<true>(z);
        const float invP = 1.0f / 4096.0f;   // 2/8192: middle sandwich factor folded in
        const size_t ch1a = ((size_t)rA * 2 + 1) * PP;
        const size_t ch1b = ((size_t)rB * 2 + 1) * PP;
#pragma unroll
        for (int q = 0; q < 16; ++q) {
            int p = off + (q << 9);
            float hA = z[rv[q]].x * invP;
            float hB = z[rv[q]].y * invP;
            __stcs(out + ch1a + (PP - 1 - p), hA);
            __stcs(out + raw_off + ch1a + p, hA);
            __stcs(out + ch1b + (PP - 1 - p), hB);
            __stcs(out + raw_off + ch1b + p, hB);
        }
    }
}

extern "C" void kernel_launch(void* const* d_in, const int* in_sizes, int n_in,
                              void* d_out, int out_size) {
    const float* g_start = (const float*)d_in[0];
    const float* g_end   = (const float*)d_in[1];
    const float* g_std   = (const float*)d_in[2];
    const float* g_lb    = (const float*)d_in[3];
    const float* g_ub    = (const float*)d_in[4];
    const int*   g_win   = (const int*)  d_in[5];
    const float* g_scale = (const float*)d_in[6];
    const float* g_noise = (const float*)d_in[7];
    const float* g_omit  = (const float*)d_in[8];
    const float* g_ppm   = (const float*)d_in[9];
    const float* g_range = (const float*)d_in[10];
    float* out = (float*)d_out;

    cudaFuncSetAttribute(pipeline_kernel,
                         cudaFuncAttributeMaxDynamicSharedMemorySize, SMEM_TOTAL);
    pipeline_kernel<<<NB / 2, NT, SMEM_TOTAL>>>(
        g_start, g_end, g_std, g_lb, g_ub, g_win, g_scale, g_noise,
        g_omit, g_ppm, g_range, out);
}